// round 11
// baseline (speedup 1.0000x reference)
#include <cuda_runtime.h>
#include <cuda_bf16.h>
#include <cstdint>
#include <math.h>

// Problem sizes (fixed)
#define NN    8192
#define F_IN  512
#define H1D   256
#define H2D   128
#define WCATN 512   // 4*H2

typedef __nv_bfloat16 bf16;

// ---------------- scratch (device globals; no allocation allowed) -----------
// bf16 hi/lo planes stored TILED+SWIZZLED: logical [R][K] -> tiles (R/128)x(K/64),
// each tile 8192 bf16 = 16 KB contiguous, SW128-swizzled within.
__device__ bf16 g_adjh[(size_t)NN * NN];
__device__ bf16 g_adjl[(size_t)NN * NN];
__device__ bf16 g_xh[NN * F_IN];
__device__ bf16 g_xl[NN * F_IN];
__device__ bf16 g_W1th[H1D * F_IN];
__device__ bf16 g_W1tl[H1D * F_IN];
__device__ bf16 g_Wcatth[WCATN * H1D];
__device__ bf16 g_Wcattl[WCATN * H1D];
__device__ bf16 g_Wlth[H2D * H2D];
__device__ bf16 g_Wltl[H2D * H2D];
__device__ bf16 g_T0th[H1D * NN];
__device__ bf16 g_T0tl[H1D * NN];
__device__ bf16 g_h1h[NN * H1D];
__device__ bf16 g_h1l[NN * H1D];
__device__ bf16 g_T1th[WCATN * NN];
__device__ bf16 g_T1tl[WCATN * NN];
__device__ bf16 g_zh[NN * H2D];
__device__ bf16 g_zl[NN * H2D];
__device__ bf16 g_uzh[NN * H2D];
__device__ bf16 g_uzl[NN * H2D];
__device__ float g_Mb[NN * WCATN];
__device__ float g_prec[H2D];
__device__ float g_wmu[H2D];
__device__ float g_gmu[H2D];
__device__ float g_glv[H2D];
__device__ float g_crow[H2D];

// ---------------- common tile config ----------------------------------------
#define BKC        64
#define NTHR       256
#define SM_HDR     1024
#define PT_BYTES   16384                 // one stored 128x64 bf16 tile

#if defined(__CUDA_ARCH_FEAT_SM103_ALL) || defined(__CUDA_ARCH_FEAT_SM100_ALL)
#define HAVE_TCGEN05 1
#else
#define HAVE_TCGEN05 0
#endif

#define MB_FULL(base, s)  ((base) + 16 + 8 * (s))
#define MB_EMPTY(base, s) ((base) + 48 + 8 * (s))

// ---------------- tiled-plane addressing helpers -----------------------------
__host__ __device__ __forceinline__ size_t pt_base(int r, int k, int K) {
    return (((size_t)(r >> 7) * (size_t)(K >> 6)) + (size_t)(k >> 6)) << 13; // *8192
}
__device__ __forceinline__ uint32_t pt_sw(int rin, int kin) {
    uint32_t off = (uint32_t)(rin * 128 + kin * 2);
    return off ^ ((off >> 3) & 0x70);
}

__device__ __forceinline__ void split_bf(float v, bf16& h, bf16& l) {
    h = __float2bfloat16(v);
    l = __float2bfloat16(v - __bfloat162float(h));
}
__device__ __forceinline__ uint32_t pack2(bf16 a, bf16 b) {
    __nv_bfloat162 p = __halves2bfloat162(a, b);
    return *(uint32_t*)&p;
}
__device__ __forceinline__ uint32_t elect_one_pred() {
    uint32_t pred;
    asm volatile(
        "{\n\t.reg .pred p;\n\telect.sync _|p, 0xFFFFFFFF;\n\tselp.b32 %0, 1, 0, p;\n\t}"
        : "=r"(pred));
    return pred;
}
__device__ __forceinline__ uint32_t smem_to_u32(const void* smem_ptr) {
    uint32_t addr;
    asm("{ .reg .u64 tmp; cvta.to.shared.u64 tmp, %1; cvt.u32.u64 %0, tmp; }"
        : "=r"(addr) : "l"(smem_ptr));
    return addr;
}

#if HAVE_TCGEN05

#define MBARRIER_INIT(mbar, count) \
    asm volatile("mbarrier.init.shared.b64 [%0], %1;" \
        :: "r"((uint32_t)(mbar)), "r"((uint32_t)(count)) : "memory")
#define MBARRIER_EXPECT_TX(mbar, tx) \
    asm volatile("mbarrier.arrive.expect_tx.shared.b64 _, [%0], %1;" \
        :: "r"((uint32_t)(mbar)), "r"((uint32_t)(tx)) : "memory")
#define BULK_G2S(dst_smem, src_gmem, bytes, mbar) \
    asm volatile("cp.async.bulk.shared::cta.global.mbarrier::complete_tx::bytes " \
        "[%0], [%1], %2, [%3];" \
        :: "r"((uint32_t)(dst_smem)), "l"(src_gmem), "r"((uint32_t)(bytes)), \
           "r"((uint32_t)(mbar)) : "memory")
#define MBARRIER_WAIT_PARITY(mbar_smem_addr, phase_parity) do { \
    uint32_t _mbar = (uint32_t)(mbar_smem_addr); \
    uint32_t _parity = (uint32_t)(phase_parity); \
    uint32_t _done; \
    asm volatile( \
        "{\n\t.reg .pred p;\n\t" \
        "mbarrier.try_wait.parity.acquire.cta.shared::cta.b64 p, [%1], %2;\n\t" \
        "selp.b32 %0, 1, 0, p;\n\t}" \
        : "=r"(_done) : "r"(_mbar), "r"(_parity) : "memory"); \
    if (!_done) { \
        asm volatile( \
            "{\n\t.reg .pred P1;\n\t" \
            "WAIT_LOOP_%=:\n\t" \
            "mbarrier.try_wait.parity.acquire.cta.shared::cta.b64 P1, [%0], %1, 0x989680;\n\t" \
            "@P1 bra.uni WAIT_DONE_%=;\n\t" \
            "bra.uni WAIT_LOOP_%=;\n\t" \
            "WAIT_DONE_%=:\n\t}" \
            :: "r"(_mbar), "r"(_parity) : "memory"); \
    } \
} while(0)

#define TCGEN05_ALLOC(smem_result_addr, nCols) \
    asm volatile("tcgen05.alloc.cta_group::1.sync.aligned.shared::cta.b32 [%0], %1;" \
        :: "r"((uint32_t)(smem_result_addr)), "r"((uint32_t)(nCols)) : "memory")
#define TCGEN05_DEALLOC(tmem_addr, nCols) \
    asm volatile("tcgen05.dealloc.cta_group::1.sync.aligned.b32 %0, %1;" \
        :: "r"(tmem_addr), "r"((uint32_t)(nCols)))
#define TCGEN05_RELINQUISH() \
    asm volatile("tcgen05.relinquish_alloc_permit.cta_group::1.sync.aligned;")
#define TCGEN05_COMMIT(mbar_smem_addr) \
    asm volatile("tcgen05.commit.cta_group::1.mbarrier::arrive::one.shared::cluster.b64 [%0];" \
        :: "r"((uint32_t)(mbar_smem_addr)) : "memory")
#define TCGEN05_WAIT_LD() \
    asm volatile("tcgen05.wait::ld.sync.aligned;" ::: "memory")
#define TCGEN05_FENCE_AFTER() \
    asm volatile("tcgen05.fence::after_thread_sync;" ::: "memory")

#define TCGEN05_LD_32X32B_X32(r, tmem_addr) \
    asm volatile( \
        "tcgen05.ld.sync.aligned.32x32b.x32.b32 " \
        "{%0, %1, %2, %3, %4, %5, %6, %7, " \
        " %8, %9, %10, %11, %12, %13, %14, %15, " \
        " %16, %17, %18, %19, %20, %21, %22, %23, " \
        " %24, %25, %26, %27, %28, %29, %30, %31}, [%32];" \
        : "=r"((r)[0]),  "=r"((r)[1]),  "=r"((r)[2]),  "=r"((r)[3]), \
          "=r"((r)[4]),  "=r"((r)[5]),  "=r"((r)[6]),  "=r"((r)[7]), \
          "=r"((r)[8]),  "=r"((r)[9]),  "=r"((r)[10]), "=r"((r)[11]), \
          "=r"((r)[12]), "=r"((r)[13]), "=r"((r)[14]), "=r"((r)[15]), \
          "=r"((r)[16]), "=r"((r)[17]), "=r"((r)[18]), "=r"((r)[19]), \
          "=r"((r)[20]), "=r"((r)[21]), "=r"((r)[22]), "=r"((r)[23]), \
          "=r"((r)[24]), "=r"((r)[25]), "=r"((r)[26]), "=r"((r)[27]), \
          "=r"((r)[28]), "=r"((r)[29]), "=r"((r)[30]), "=r"((r)[31]) \
        : "r"(tmem_addr))

static constexpr uint64_t SMEM_DESC_BASE_SW128 =
    (uint64_t(2)  << 61) | (uint64_t(1) << 46) | (uint64_t(64) << 32) | (uint64_t(1) << 16);
#define MAKE_SMEM_DESC(base_addr) \
    (SMEM_DESC_BASE_SW128 | ((uint64_t)((base_addr) >> 4) & 0x3FFF))

__device__ __forceinline__ void mma_bf16(uint32_t d, uint64_t ad, uint64_t bd,
                                         uint32_t idesc, uint32_t en) {
    asm volatile(
        "{\n\t.reg .pred p;\n\tsetp.ne.u32 p, %4, 0;\n\t"
        "tcgen05.mma.cta_group::1.kind::f16 [%0], %1, %2, %3, {%5,%5,%5,%5}, p;\n\t}"
        :: "r"(d), "l"(ad), "l"(bd), "r"(idesc), "r"(en), "r"(0u) : "memory");
}
#endif  // HAVE_TCGEN05

// ---------------- GEMM: C = A[M,K] @ Bt[N,K]^T via tiled bf16 planes --------
// TN: output tile N (128 or 256); NS: ring depth. M tile fixed 128.
// epi: 0 none, 1 relu, 2 add g_crow; transC: output transposed
template<int TN, int NS>
__global__ void __launch_bounds__(NTHR, 1)
gemm_bf(const bf16* __restrict__ Ah, const bf16* __restrict__ Al, int lda,
        const bf16* __restrict__ Bh, const bf16* __restrict__ Bl, int ldb,
        float* __restrict__ C, bf16* __restrict__ Ch, bf16* __restrict__ Cl,
        int ldc, int K, int epi, int transC)
{
    extern __shared__ char smem[];
    const int tid = threadIdx.x;
    const int col0 = blockIdx.x * TN;
    const int row0 = blockIdx.y * 128;

    constexpr int NBT = TN / 128;                       // B 128-row tiles per stage
    constexpr int STAGE_BYTES = 2 * PT_BYTES + 2 * NBT * PT_BYTES;

#if HAVE_TCGEN05
    const uint32_t smem_base = smem_to_u32(smem);
    const int wid = tid >> 5;
    const int lid = tid & 31;

    constexpr uint32_t IDESC =
        (1u << 4) | (1u << 7) | (1u << 10) | ((TN / 8) << 17) | ((128 / 16) << 24);

    if (wid == 0) TCGEN05_ALLOC(smem_base + 0, TN);
    if (tid == 0) {
#pragma unroll
        for (int s = 0; s < NS; ++s) {
            MBARRIER_INIT(MB_FULL(smem_base, s), 1);   // expect_tx arrive
            MBARRIER_INIT(MB_EMPTY(smem_base, s), 1);  // tcgen05.commit
        }
    }
    __syncthreads();
    uint32_t tmem;
    asm volatile("ld.shared.b32 %0, [%1];" : "=r"(tmem) : "r"(smem_base));

    const int nch = K / BKC;

    if (wid == 0 && elect_one_pred()) {
        // chunk loader: stage layout [Ah][Al][Bh tiles...][Bl tiles...]
        auto load_chunk = [&](int n, int s) {
            uint32_t dst = smem_base + SM_HDR + s * STAGE_BYTES;
            uint32_t fb = MB_FULL(smem_base, s);
            MBARRIER_EXPECT_TX(fb, STAGE_BYTES);
            BULK_G2S(dst + 0 * PT_BYTES, Ah + pt_base(row0, n * BKC, lda), PT_BYTES, fb);
            BULK_G2S(dst + 1 * PT_BYTES, Al + pt_base(row0, n * BKC, lda), PT_BYTES, fb);
#pragma unroll
            for (int t = 0; t < NBT; ++t) {
                BULK_G2S(dst + (2 + t) * PT_BYTES,
                         Bh + pt_base(col0 + t * 128, n * BKC, ldb), PT_BYTES, fb);
                BULK_G2S(dst + (2 + NBT + t) * PT_BYTES,
                         Bl + pt_base(col0 + t * 128, n * BKC, ldb), PT_BYTES, fb);
            }
        };

        const int P = (nch < NS - 1) ? nch : (NS - 1);
        for (int p = 0; p < P; ++p) load_chunk(p, p);

        for (int c = 0; c < nch; ++c) {
            const int ci = c / NS;
            const int s  = c - ci * NS;
            MBARRIER_WAIT_PARITY(MB_FULL(smem_base, s), ci & 1);
            uint32_t stg = smem_base + SM_HDR + s * STAGE_BYTES;
            uint64_t ah = MAKE_SMEM_DESC(stg);
            uint64_t al = ah + (PT_BYTES >> 4);
            uint64_t bh = ah + 2 * (PT_BYTES >> 4);
            uint64_t bl = bh + NBT * (PT_BYTES >> 4);
            uint32_t en = (c > 0) ? 1u : 0u;
#pragma unroll
            for (int st = 0; st < 4; ++st) {     // 4 k-steps of 16 bf16
                mma_bf16(tmem, ah + 2 * st, bh + 2 * st, IDESC, en); en = 1u;
                mma_bf16(tmem, ah + 2 * st, bl + 2 * st, IDESC, 1u);
                mma_bf16(tmem, al + 2 * st, bh + 2 * st, IDESC, 1u);
            }
            TCGEN05_COMMIT(MB_EMPTY(smem_base, s));
            // early refill: chunk c+NS-1 into stage (c-1)%NS (free once chunk c-1 done)
            const int n = c + NS - 1;
            if (n < nch) {
                if (c >= 1)
                    MBARRIER_WAIT_PARITY(MB_EMPTY(smem_base, (c - 1) % NS), ((c - 1) / NS) & 1);
                load_chunk(n, n % NS);
            }
        }
        // final wait: lap-free ONLY for this thread.
        const int cl = nch - 1;
        MBARRIER_WAIT_PARITY(MB_EMPTY(smem_base, cl % NS), (cl / NS) & 1);
    }
    // rendezvous before epilogue
    __syncthreads();
    TCGEN05_FENCE_AFTER();

    // epilogue: 8 warps; warps 0-3 = first half of col groups, 4-7 = second half
    {
        constexpr int NGRP = TN / 32;
        constexpr int HALF = NGRP / 2;
        const int wg = wid >> 2;
        const int row = row0 + (wid & 3) * 32 + lid;
#pragma unroll
        for (int gg = 0; gg < HALF; ++gg) {
            const int g = wg * HALF + gg;
            uint32_t r[32];
            TCGEN05_LD_32X32B_X32(r, tmem + g * 32);
            TCGEN05_WAIT_LD();
            if (C) {
#pragma unroll
                for (int j = 0; j < 32; j += 4) {
                    const int col = col0 + g * 32 + j;
                    float v0 = __uint_as_float(r[j + 0]);
                    float v1 = __uint_as_float(r[j + 1]);
                    float v2 = __uint_as_float(r[j + 2]);
                    float v3 = __uint_as_float(r[j + 3]);
                    if (epi == 1) {
                        v0 = fmaxf(v0, 0.0f); v1 = fmaxf(v1, 0.0f);
                        v2 = fmaxf(v2, 0.0f); v3 = fmaxf(v3, 0.0f);
                    } else if (epi == 2) {
                        v0 += g_crow[col + 0]; v1 += g_crow[col + 1];
                        v2 += g_crow[col + 2]; v3 += g_crow[col + 3];
                    }
                    if (!transC) {
                        *(float4*)(C + (size_t)row * ldc + col) = make_float4(v0, v1, v2, v3);
                    } else {
                        C[(size_t)(col + 0) * ldc + row] = v0;
                        C[(size_t)(col + 1) * ldc + row] = v1;
                        C[(size_t)(col + 2) * ldc + row] = v2;
                        C[(size_t)(col + 3) * ldc + row] = v3;
                    }
                }
            }
            if (Ch) {
#pragma unroll
                for (int j = 0; j < 32; j += 8) {
                    const int colb = col0 + g * 32 + j;
                    float v[8];
#pragma unroll
                    for (int q = 0; q < 8; ++q) {
                        float t = __uint_as_float(r[j + q]);
                        if (epi == 1) t = fmaxf(t, 0.0f);
                        else if (epi == 2) t += g_crow[colb + q];
                        v[q] = t;
                    }
                    bf16 h[8], l[8];
#pragma unroll
                    for (int q = 0; q < 8; ++q) split_bf(v[q], h[q], l[q]);
                    if (!transC) {
                        size_t tb = pt_base(row, colb, ldc);
                        uint32_t sw = pt_sw(row & 127, colb & 63);
                        uint4 hq = make_uint4(pack2(h[0], h[1]), pack2(h[2], h[3]),
                                              pack2(h[4], h[5]), pack2(h[6], h[7]));
                        uint4 lq = make_uint4(pack2(l[0], l[1]), pack2(l[2], l[3]),
                                              pack2(l[4], l[5]), pack2(l[6], l[7]));
                        *(uint4*)((char*)(Ch + tb) + sw) = hq;
                        *(uint4*)((char*)(Cl + tb) + sw) = lq;
                    } else {
#pragma unroll
                        for (int q = 0; q < 8; ++q) {
                            const int col = colb + q;
                            size_t tb = pt_base(col, row, ldc);
                            uint32_t sw = pt_sw(col & 127, row & 63);
                            *(bf16*)((char*)(Ch + tb) + sw) = h[q];
                            *(bf16*)((char*)(Cl + tb) + sw) = l[q];
                        }
                    }
                }
            }
        }
    }
    __syncthreads();
    if (tid == 0) {
#pragma unroll
        for (int s = 0; s < NS; ++s) {
            asm volatile("mbarrier.inval.shared.b64 [%0];" :: "r"(MB_FULL(smem_base, s)) : "memory");
            asm volatile("mbarrier.inval.shared.b64 [%0];" :: "r"(MB_EMPTY(smem_base, s)) : "memory");
        }
    }
    __syncthreads();
    if (wid == 0) {
        TCGEN05_RELINQUISH();
        TCGEN05_DEALLOC(tmem, TN);
    }

#else
    // ------------- fallback (compile-only on non-103a passes) ---------------
    float* As = (float*)smem;                 // [16][128]
    float* Bs = As + 16 * 128;
    const int tx = tid & 15;
    const int ty = tid >> 4;

    auto rdp = [](const bf16* P, int r, int k, int Kl) {
        size_t tb = pt_base(r, k, Kl);
        uint32_t sw = pt_sw(r & 127, k & 63);
        return __bfloat162float(*(const bf16*)((const char*)(P + tb) + sw));
    };
    for (int cb = 0; cb < TN / 128; ++cb) {
        const int cbase = col0 + cb * 128;
        float acc[8][8];
#pragma unroll
        for (int i = 0; i < 8; i++)
#pragma unroll
            for (int j = 0; j < 8; j++) acc[i][j] = 0.0f;
        for (int k0 = 0; k0 < K; k0 += 16) {
            __syncthreads();
            for (int f = tid; f < 16 * 128; f += NTHR) {
                int kk = f >> 7, m = f & 127;
                As[kk * 128 + m] = rdp(Ah, row0 + m, k0 + kk, lda) + rdp(Al, row0 + m, k0 + kk, lda);
                Bs[kk * 128 + m] = rdp(Bh, cbase + m, k0 + kk, ldb) + rdp(Bl, cbase + m, k0 + kk, ldb);
            }
            __syncthreads();
#pragma unroll
            for (int kk = 0; kk < 16; kk++) {
                float a[8], b[8];
#pragma unroll
                for (int i = 0; i < 8; i++) a[i] = As[kk * 128 + ty * 8 + i];
#pragma unroll
                for (int j = 0; j < 8; j++) b[j] = Bs[kk * 128 + tx * 8 + j];
#pragma unroll
                for (int i = 0; i < 8; i++)
#pragma unroll
                    for (int j = 0; j < 8; j++) acc[i][j] = fmaf(a[i], b[j], acc[i][j]);
            }
        }
#pragma unroll
        for (int i = 0; i < 8; i++) {
            const int row = row0 + ty * 8 + i;
#pragma unroll
            for (int j = 0; j < 8; j++) {
                const int col = cbase + tx * 8 + j;
                float v = acc[i][j];
                if (epi == 1) v = fmaxf(v, 0.0f);
                else if (epi == 2) v += g_crow[col];
                if (C) {
                    size_t idx = transC ? ((size_t)col * ldc + row) : ((size_t)row * ldc + col);
                    C[idx] = v;
                }
                if (Ch) {
                    bf16 h, l; split_bf(v, h, l);
                    int pr = transC ? col : row;
                    int pk = transC ? row : col;
                    size_t tb = pt_base(pr, pk, ldc);
                    uint32_t sw = pt_sw(pr & 127, pk & 63);
                    *(bf16*)((char*)(Ch + tb) + sw) = h;
                    *(bf16*)((char*)(Cl + tb) + sw) = l;
                }
            }
        }
        __syncthreads();
    }
#endif
}

// ---------------- split kernels (write tiled plane layout) -------------------
__global__ void k_split_tiled(const float* __restrict__ src, bf16* __restrict__ dh,
                              bf16* __restrict__ dl, int R, int K) {
    size_t idx = (size_t)blockIdx.x * blockDim.x + threadIdx.x;
    size_t n8 = (size_t)K >> 3;
    if (idx >= (size_t)R * n8) return;
    int r = (int)(idx / n8);
    int k = (int)(idx % n8) * 8;
    float4 a = *(const float4*)(src + (size_t)r * K + k);
    float4 b = *(const float4*)(src + (size_t)r * K + k + 4);
    bf16 h[8], l[8];
    split_bf(a.x, h[0], l[0]); split_bf(a.y, h[1], l[1]);
    split_bf(a.z, h[2], l[2]); split_bf(a.w, h[3], l[3]);
    split_bf(b.x, h[4], l[4]); split_bf(b.y, h[5], l[5]);
    split_bf(b.z, h[6], l[6]); split_bf(b.w, h[7], l[7]);
    size_t tb = pt_base(r, k, K);
    uint32_t sw = pt_sw(r & 127, k & 63);
    *(uint4*)((char*)(dh + tb) + sw) = make_uint4(pack2(h[0], h[1]), pack2(h[2], h[3]),
                                                  pack2(h[4], h[5]), pack2(h[6], h[7]));
    *(uint4*)((char*)(dl + tb) + sw) = make_uint4(pack2(l[0], l[1]), pack2(l[2], l[3]),
                                                  pack2(l[4], l[5]), pack2(l[6], l[7]));
}

__global__ void k_split_T(const float* __restrict__ src, bf16* __restrict__ dh,
                          bf16* __restrict__ dl, int R, int K) {
    int idx = blockIdx.x * blockDim.x + threadIdx.x;
    int n8 = K >> 3;
    if (idx >= R * n8) return;
    int r = idx / n8;
    int k = (idx % n8) * 8;
    bf16 h[8], l[8];
#pragma unroll
    for (int q = 0; q < 8; ++q) split_bf(src[(size_t)(k + q) * R + r], h[q], l[q]);
    size_t tb = pt_base(r, k, K);
    uint32_t sw = pt_sw(r & 127, k & 63);
    *(uint4*)((char*)(dh + tb) + sw) = make_uint4(pack2(h[0], h[1]), pack2(h[2], h[3]),
                                                  pack2(h[4], h[5]), pack2(h[6], h[7]));
    *(uint4*)((char*)(dl + tb) + sw) = make_uint4(pack2(l[0], l[1]), pack2(l[2], l[3]),
                                                  pack2(l[4], l[5]), pack2(l[6], l[7]));
}

__global__ void k_split_wcatt(const float* __restrict__ W2, const float* __restrict__ W3,
                              const float* __restrict__ W4, const float* __restrict__ W5,
                              bf16* __restrict__ dh, bf16* __restrict__ dl) {
    int idx = blockIdx.x * blockDim.x + threadIdx.x;
    int n8 = H1D >> 3;
    if (idx >= WCATN * n8) return;
    int n = idx / n8;
    int k = (idx % n8) * 8;
    int sel = n >> 7, nn = n & (H2D - 1);
    const float* W = (sel == 0) ? W2 : (sel == 1) ? W3 : (sel == 2) ? W4 : W5;
    bf16 h[8], l[8];
#pragma unroll
    for (int q = 0; q < 8; ++q) split_bf(W[(size_t)(k + q) * H2D + nn], h[q], l[q]);
    size_t tb = pt_base(n, k, H1D);
    uint32_t sw = pt_sw(n & 127, k & 63);
    *(uint4*)((char*)(dh + tb) + sw) = make_uint4(pack2(h[0], h[1]), pack2(h[2], h[3]),
                                                  pack2(h[4], h[5]), pack2(h[6], h[7]));
    *(uint4*)((char*)(dl + tb) + sw) = make_uint4(pack2(l[0], l[1]), pack2(l[2], l[3]),
                                                  pack2(l[4], l[5]), pack2(l[6], l[7]));
}

__global__ void k_z(const float* __restrict__ Mb, const float* __restrict__ eps_z,
                    float* __restrict__ out_z, float* __restrict__ out_mu,
                    float* __restrict__ out_lv, bf16* __restrict__ zh,
                    bf16* __restrict__ zl) {
    int idx = blockIdx.x * blockDim.x + threadIdx.x;
    if (idx >= NN * (H2D / 8)) return;
    int i = idx / (H2D / 8);
    int j = (idx % (H2D / 8)) * 8;
    float4 mu0 = *(const float4*)(Mb + (size_t)i * WCATN + j);
    float4 mu1 = *(const float4*)(Mb + (size_t)i * WCATN + j + 4);
    float4 lv0 = *(const float4*)(Mb + (size_t)i * WCATN + H2D + j);
    float4 lv1 = *(const float4*)(Mb + (size_t)i * WCATN + H2D + j + 4);
    float4 e0 = *(const float4*)(eps_z + (size_t)i * H2D + j);
    float4 e1 = *(const float4*)(eps_z + (size_t)i * H2D + j + 4);
    *(float4*)(out_mu + (size_t)i * H2D + j) = mu0;
    *(float4*)(out_mu + (size_t)i * H2D + j + 4) = mu1;
    *(float4*)(out_lv + (size_t)i * H2D + j) = lv0;
    *(float4*)(out_lv + (size_t)i * H2D + j + 4) = lv1;
    float z[8];
    z[0] = e0.x * expf(lv0.x) + mu0.x; z[1] = e0.y * expf(lv0.y) + mu0.y;
    z[2] = e0.z * expf(lv0.z) + mu0.z; z[3] = e0.w * expf(lv0.w) + mu0.w;
    z[4] = e1.x * expf(lv1.x) + mu1.x; z[5] = e1.y * expf(lv1.y) + mu1.y;
    z[6] = e1.z * expf(lv1.z) + mu1.z; z[7] = e1.w * expf(lv1.w) + mu1.w;
    *(float4*)(out_z + (size_t)i * H2D + j) = make_float4(z[0], z[1], z[2], z[3]);
    *(float4*)(out_z + (size_t)i * H2D + j + 4) = make_float4(z[4], z[5], z[6], z[7]);
    bf16 h[8], l[8];
#pragma unroll
    for (int q = 0; q < 8; ++q) split_bf(z[q], h[q], l[q]);
    size_t tb = pt_base(i, j, H2D);
    uint32_t sw = pt_sw(i & 127, j & 63);
    *(uint4*)((char*)(zh + tb) + sw) = make_uint4(pack2(h[0], h[1]), pack2(h[2], h[3]),
                                                  pack2(h[4], h[5]), pack2(h[6], h[7]));
    *(uint4*)((char*)(zl + tb) + sw) = make_uint4(pack2(l[0], l[1]), pack2(l[2], l[3]),
                                                  pack2(l[4], l[5]), pack2(l[6], l[7]));
}

__global__ void k_reduce(const float* __restrict__ Mb) {
    __shared__ float s1[256];
    __shared__ float s2[256];
    int j = blockIdx.x, t = threadIdx.x;
    float a = 0.0f, b = 0.0f;
    for (int i = t; i < NN; i += 256) {
        float cm = Mb[(size_t)i * WCATN + 2 * H2D + j];
        float cl = Mb[(size_t)i * WCATN + 3 * H2D + j];
        float var = expf(cl);
        if (var == 0.0f) var = 1e-6f;
        float inv = 1.0f / var;
        a += inv;
        b += cm * inv;
    }
    s1[t] = a; s2[t] = b;
    __syncthreads();
    for (int s = 128; s > 0; s >>= 1) {
        if (t < s) { s1[t] += s1[t + s]; s2[t] += s2[t + s]; }
        __syncthreads();
    }
    if (t == 0) { g_prec[j] = s1[0]; g_wmu[j] = s2[0]; }
}

__global__ void k_final(const float* __restrict__ eps_g, const float* __restrict__ Wl,
                        const float* __restrict__ bl) {
    __shared__ float cl_sh[H2D];
    int j = threadIdx.x;
    float gvar = 1.0f / g_prec[j];
    float gmu = gvar * g_wmu[j];
    float gv = (gvar == 0.0f) ? 1e-6f : gvar;
    float glv = logf(gv);
    float cl = gmu + expf(0.5f * glv) * eps_g[j];
    g_gmu[j] = gmu;
    g_glv[j] = glv;
    cl_sh[j] = cl;
    __syncthreads();
    float s = bl[j];
#pragma unroll 8
    for (int k = 0; k < H2D; k++)
        s = fmaf(cl_sh[k], Wl[(H2D + k) * H2D + j], s);
    g_crow[j] = s;
}

__global__ void k_bcast(float* __restrict__ out_gmu, float* __restrict__ out_glv) {
    int idx = blockIdx.x * blockDim.x + threadIdx.x;
    if (idx >= NN * H2D) return;
    int j = idx & (H2D - 1);
    out_gmu[idx] = g_gmu[j];
    out_glv[idx] = g_glv[j];
}

// ---------------- launch ----------------------------------------------------
extern "C" void kernel_launch(void* const* d_in, const int* in_sizes, int n_in,
                              void* d_out, int out_size)
{
    const float* x     = (const float*)d_in[0];
    const float* adj   = (const float*)d_in[1];
    const float* W1    = (const float*)d_in[2];
    const float* W2    = (const float*)d_in[3];
    const float* W3    = (const float*)d_in[4];
    const float* W4    = (const float*)d_in[5];
    const float* W5    = (const float*)d_in[6];
    const float* Wl    = (const float*)d_in[7];
    const float* bl    = (const float*)d_in[8];
    const float* eps_z = (const float*)d_in[9];
    const float* eps_g = (const float*)d_in[10];

    float* out = (float*)d_out;
    float* out_recon = out;
    float* out_z     = out + (size_t)NN * NN;
    float* out_mu    = out_z  + (size_t)NN * H2D;
    float* out_lv    = out_mu + (size_t)NN * H2D;
    float* out_gmu   = out_lv + (size_t)NN * H2D;
    float* out_glv   = out_gmu + (size_t)NN * H2D;

    bf16 *adjh, *adjl, *xh, *xl, *W1th, *W1tl, *Wcatth, *Wcattl, *Wlth, *Wltl;
    bf16 *T0th, *T0tl, *h1h, *h1l, *T1th, *T1tl, *zh, *zl, *uzh, *uzl;
    float *Mb;
    cudaGetSymbolAddress((void**)&adjh,   g_adjh);
    cudaGetSymbolAddress((void**)&adjl,   g_adjl);
    cudaGetSymbolAddress((void**)&xh,     g_xh);
    cudaGetSymbolAddress((void**)&xl,     g_xl);
    cudaGetSymbolAddress((void**)&W1th,   g_W1th);
    cudaGetSymbolAddress((void**)&W1tl,   g_W1tl);
    cudaGetSymbolAddress((void**)&Wcatth, g_Wcatth);
    cudaGetSymbolAddress((void**)&Wcattl, g_Wcattl);
    cudaGetSymbolAddress((void**)&Wlth,   g_Wlth);
    cudaGetSymbolAddress((void**)&Wltl,   g_Wltl);
    cudaGetSymbolAddress((void**)&T0th,   g_T0th);
    cudaGetSymbolAddress((void**)&T0tl,   g_T0tl);
    cudaGetSymbolAddress((void**)&h1h,    g_h1h);
    cudaGetSymbolAddress((void**)&h1l,    g_h1l);
    cudaGetSymbolAddress((void**)&T1th,   g_T1th);
    cudaGetSymbolAddress((void**)&T1tl,   g_T1tl);
    cudaGetSymbolAddress((void**)&zh,     g_zh);
    cudaGetSymbolAddress((void**)&zl,     g_zl);
    cudaGetSymbolAddress((void**)&uzh,    g_uzh);
    cudaGetSymbolAddress((void**)&uzl,    g_uzl);
    cudaGetSymbolAddress((void**)&Mb,     g_Mb);

    // smem: both variants = 1024 + {3*64KB | 2*96KB} = 197632 B
    const int SMEM128 = SM_HDR + 3 * (2 * PT_BYTES + 2 * PT_BYTES);
    const int SMEM256 = SM_HDR + 2 * (2 * PT_BYTES + 4 * PT_BYTES);
    cudaFuncSetAttribute(gemm_bf<128, 3>, cudaFuncAttributeMaxDynamicSharedMemorySize, SMEM128);
    cudaFuncSetAttribute(gemm_bf<256, 2>, cudaFuncAttributeMaxDynamicSharedMemorySize, SMEM256);

    // input splits (tiled plane layout)
    {
        size_t na = (size_t)NN * (NN / 8);
        k_split_tiled<<<(unsigned)((na + 255) / 256), 256>>>(adj, adjh, adjl, NN, NN);
        size_t nx = (size_t)NN * (F_IN / 8);
        k_split_tiled<<<(unsigned)((nx + 255) / 256), 256>>>(x, xh, xl, NN, F_IN);
        k_split_T<<<(H1D * F_IN / 8 + 255) / 256, 256>>>(W1, W1th, W1tl, H1D, F_IN);
        k_split_wcatt<<<(WCATN * H1D / 8 + 255) / 256, 256>>>(W2, W3, W4, W5, Wcatth, Wcattl);
        k_split_T<<<(H2D * H2D / 8 + 255) / 256, 256>>>(Wl, Wlth, Wltl, H2D, H2D);
    }

    // G1: T0t planes = (x @ W1)^T   M=8192 N=256 K=512
    gemm_bf<128, 3><<<dim3(H1D / 128, NN / 128), NTHR, SMEM128>>>(
        xh, xl, F_IN, W1th, W1tl, F_IN, nullptr, T0th, T0tl, NN, F_IN, 0, 1);
    // G2: h1 planes = relu(adj @ T0)  M=8192 N=256 K=8192
    gemm_bf<128, 3><<<dim3(H1D / 128, NN / 128), NTHR, SMEM128>>>(
        adjh, adjl, NN, T0th, T0tl, NN, nullptr, h1h, h1l, H1D, NN, 1, 0);
    // G3: T1t planes = (h1 @ Wcat)^T  M=8192 N=512 K=256  (256-wide tiles)
    gemm_bf<256, 2><<<dim3(WCATN / 256, NN / 128), NTHR, SMEM256>>>(
        h1h, h1l, H1D, Wcatth, Wcattl, H1D, nullptr, T1th, T1tl, NN, H1D, 0, 1);
    // G4: Mb = adj @ T1 (fp32)        M=8192 N=512 K=8192 (256-wide tiles)
    gemm_bf<256, 2><<<dim3(WCATN / 256, NN / 128), NTHR, SMEM256>>>(
        adjh, adjl, NN, T1th, T1tl, NN, Mb, nullptr, nullptr, WCATN, NN, 0, 0);

    // z / mu / logvar (+ z planes) + group evidence
    k_z     <<<(NN * (H2D / 8) + 255) / 256, 256>>>(Mb, eps_z, out_z, out_mu, out_lv, zh, zl);
    k_reduce<<<H2D, 256>>>(Mb);
    k_final <<<1, H2D>>>(eps_g, Wl, bl);
    k_bcast <<<(NN * H2D + 255) / 256, 256>>>(out_gmu, out_glv);

    // G5: uz planes = z @ Wl_top + crow   M=8192 N=128 K=128
    gemm_bf<128, 3><<<dim3(1, NN / 128), NTHR, SMEM128>>>(
        zh, zl, H2D, Wlth, Wltl, H2D, nullptr, uzh, uzl, H2D, H2D, 2, 0);
    // G6: recon = uz @ uz^T (fp32)        M=8192 N=8192 K=128 (256-wide tiles)
    gemm_bf<256, 2><<<dim3(NN / 256, NN / 128), NTHR, SMEM256>>>(
        uzh, uzl, H2D, uzh, uzl, H2D, out_recon, nullptr, nullptr, NN, H2D, 0, 0);
}

// round 12
// speedup vs baseline: 1.1468x; 1.1468x over previous
#include <cuda_runtime.h>
#include <cuda_bf16.h>
#include <cstdint>
#include <math.h>

// Problem sizes (fixed)
#define NN    8192
#define F_IN  512
#define H1D   256
#define H2D   128
#define WCATN 512   // 4*H2

typedef __nv_bfloat16 bf16;

// ---------------- scratch (device globals; no allocation allowed) -----------
// bf16 hi/lo planes stored TILED+SWIZZLED: logical [R][K] -> tiles (R/128)x(K/64),
// each tile 8192 bf16 = 16 KB contiguous, SW128-swizzled within.
__device__ bf16 g_adjh[(size_t)NN * NN];
__device__ bf16 g_adjl[(size_t)NN * NN];
__device__ bf16 g_xh[NN * F_IN];
__device__ bf16 g_xl[NN * F_IN];
__device__ bf16 g_W1th[H1D * F_IN];
__device__ bf16 g_W1tl[H1D * F_IN];
__device__ bf16 g_Wcatth[WCATN * H1D];
__device__ bf16 g_Wcattl[WCATN * H1D];
__device__ bf16 g_Wlth[H2D * H2D];
__device__ bf16 g_Wltl[H2D * H2D];
__device__ bf16 g_T0th[H1D * NN];
__device__ bf16 g_T0tl[H1D * NN];
__device__ bf16 g_h1h[NN * H1D];
__device__ bf16 g_h1l[NN * H1D];
__device__ bf16 g_T1th[WCATN * NN];
__device__ bf16 g_T1tl[WCATN * NN];
__device__ bf16 g_zh[NN * H2D];
__device__ bf16 g_zl[NN * H2D];
__device__ bf16 g_uzh[NN * H2D];
__device__ bf16 g_uzl[NN * H2D];
__device__ float g_Mb[NN * WCATN];
__device__ float g_prec[H2D];
__device__ float g_wmu[H2D];
__device__ float g_gmu[H2D];
__device__ float g_glv[H2D];
__device__ float g_crow[H2D];

// ---------------- common tile config ----------------------------------------
#define BKC        64
#define NTHR       256
#define SM_HDR     1024
#define PT_BYTES   16384                 // one stored 128x64 bf16 tile

#if defined(__CUDA_ARCH_FEAT_SM103_ALL) || defined(__CUDA_ARCH_FEAT_SM100_ALL)
#define HAVE_TCGEN05 1
#else
#define HAVE_TCGEN05 0
#endif

#define MB_FULL(base, s)  ((base) + 16 + 8 * (s))
#define MB_EMPTY(base, s) ((base) + 48 + 8 * (s))

// ---------------- tiled-plane addressing helpers -----------------------------
__host__ __device__ __forceinline__ size_t pt_base(int r, int k, int K) {
    return (((size_t)(r >> 7) * (size_t)(K >> 6)) + (size_t)(k >> 6)) << 13; // *8192
}
__device__ __forceinline__ uint32_t pt_sw(int rin, int kin) {
    uint32_t off = (uint32_t)(rin * 128 + kin * 2);
    return off ^ ((off >> 3) & 0x70);
}

__device__ __forceinline__ void split_bf(float v, bf16& h, bf16& l) {
    h = __float2bfloat16(v);
    l = __float2bfloat16(v - __bfloat162float(h));
}
__device__ __forceinline__ uint32_t pack2(bf16 a, bf16 b) {
    __nv_bfloat162 p = __halves2bfloat162(a, b);
    return *(uint32_t*)&p;
}
__device__ __forceinline__ uint32_t elect_one_pred() {
    uint32_t pred;
    asm volatile(
        "{\n\t.reg .pred p;\n\telect.sync _|p, 0xFFFFFFFF;\n\tselp.b32 %0, 1, 0, p;\n\t}"
        : "=r"(pred));
    return pred;
}
__device__ __forceinline__ uint32_t smem_to_u32(const void* smem_ptr) {
    uint32_t addr;
    asm("{ .reg .u64 tmp; cvta.to.shared.u64 tmp, %1; cvt.u32.u64 %0, tmp; }"
        : "=r"(addr) : "l"(smem_ptr));
    return addr;
}

#if HAVE_TCGEN05

#define MBARRIER_INIT(mbar, count) \
    asm volatile("mbarrier.init.shared.b64 [%0], %1;" \
        :: "r"((uint32_t)(mbar)), "r"((uint32_t)(count)) : "memory")
#define MBARRIER_EXPECT_TX(mbar, tx) \
    asm volatile("mbarrier.arrive.expect_tx.shared.b64 _, [%0], %1;" \
        :: "r"((uint32_t)(mbar)), "r"((uint32_t)(tx)) : "memory")
#define BULK_G2S(dst_smem, src_gmem, bytes, mbar) \
    asm volatile("cp.async.bulk.shared::cta.global.mbarrier::complete_tx::bytes " \
        "[%0], [%1], %2, [%3];" \
        :: "r"((uint32_t)(dst_smem)), "l"(src_gmem), "r"((uint32_t)(bytes)), \
           "r"((uint32_t)(mbar)) : "memory")
#define MBARRIER_WAIT_PARITY(mbar_smem_addr, phase_parity) do { \
    uint32_t _mbar = (uint32_t)(mbar_smem_addr); \
    uint32_t _parity = (uint32_t)(phase_parity); \
    uint32_t _done; \
    asm volatile( \
        "{\n\t.reg .pred p;\n\t" \
        "mbarrier.try_wait.parity.acquire.cta.shared::cta.b64 p, [%1], %2;\n\t" \
        "selp.b32 %0, 1, 0, p;\n\t}" \
        : "=r"(_done) : "r"(_mbar), "r"(_parity) : "memory"); \
    if (!_done) { \
        asm volatile( \
            "{\n\t.reg .pred P1;\n\t" \
            "WAIT_LOOP_%=:\n\t" \
            "mbarrier.try_wait.parity.acquire.cta.shared::cta.b64 P1, [%0], %1, 0x989680;\n\t" \
            "@P1 bra.uni WAIT_DONE_%=;\n\t" \
            "bra.uni WAIT_LOOP_%=;\n\t" \
            "WAIT_DONE_%=:\n\t}" \
            :: "r"(_mbar), "r"(_parity) : "memory"); \
    } \
} while(0)

#define TCGEN05_ALLOC(smem_result_addr, nCols) \
    asm volatile("tcgen05.alloc.cta_group::1.sync.aligned.shared::cta.b32 [%0], %1;" \
        :: "r"((uint32_t)(smem_result_addr)), "r"((uint32_t)(nCols)) : "memory")
#define TCGEN05_DEALLOC(tmem_addr, nCols) \
    asm volatile("tcgen05.dealloc.cta_group::1.sync.aligned.b32 %0, %1;" \
        :: "r"(tmem_addr), "r"((uint32_t)(nCols)))
#define TCGEN05_RELINQUISH() \
    asm volatile("tcgen05.relinquish_alloc_permit.cta_group::1.sync.aligned;")
#define TCGEN05_COMMIT(mbar_smem_addr) \
    asm volatile("tcgen05.commit.cta_group::1.mbarrier::arrive::one.shared::cluster.b64 [%0];" \
        :: "r"((uint32_t)(mbar_smem_addr)) : "memory")
#define TCGEN05_WAIT_LD() \
    asm volatile("tcgen05.wait::ld.sync.aligned;" ::: "memory")
#define TCGEN05_FENCE_AFTER() \
    asm volatile("tcgen05.fence::after_thread_sync;" ::: "memory")

#define TCGEN05_LD_32X32B_X32(r, tmem_addr) \
    asm volatile( \
        "tcgen05.ld.sync.aligned.32x32b.x32.b32 " \
        "{%0, %1, %2, %3, %4, %5, %6, %7, " \
        " %8, %9, %10, %11, %12, %13, %14, %15, " \
        " %16, %17, %18, %19, %20, %21, %22, %23, " \
        " %24, %25, %26, %27, %28, %29, %30, %31}, [%32];" \
        : "=r"((r)[0]),  "=r"((r)[1]),  "=r"((r)[2]),  "=r"((r)[3]), \
          "=r"((r)[4]),  "=r"((r)[5]),  "=r"((r)[6]),  "=r"((r)[7]), \
          "=r"((r)[8]),  "=r"((r)[9]),  "=r"((r)[10]), "=r"((r)[11]), \
          "=r"((r)[12]), "=r"((r)[13]), "=r"((r)[14]), "=r"((r)[15]), \
          "=r"((r)[16]), "=r"((r)[17]), "=r"((r)[18]), "=r"((r)[19]), \
          "=r"((r)[20]), "=r"((r)[21]), "=r"((r)[22]), "=r"((r)[23]), \
          "=r"((r)[24]), "=r"((r)[25]), "=r"((r)[26]), "=r"((r)[27]), \
          "=r"((r)[28]), "=r"((r)[29]), "=r"((r)[30]), "=r"((r)[31]) \
        : "r"(tmem_addr))

static constexpr uint64_t SMEM_DESC_BASE_SW128 =
    (uint64_t(2)  << 61) | (uint64_t(1) << 46) | (uint64_t(64) << 32) | (uint64_t(1) << 16);
#define MAKE_SMEM_DESC(base_addr) \
    (SMEM_DESC_BASE_SW128 | ((uint64_t)((base_addr) >> 4) & 0x3FFF))

__device__ __forceinline__ void mma_bf16(uint32_t d, uint64_t ad, uint64_t bd,
                                         uint32_t idesc, uint32_t en) {
    asm volatile(
        "{\n\t.reg .pred p;\n\tsetp.ne.u32 p, %4, 0;\n\t"
        "tcgen05.mma.cta_group::1.kind::f16 [%0], %1, %2, %3, {%5,%5,%5,%5}, p;\n\t}"
        :: "r"(d), "l"(ad), "l"(bd), "r"(idesc), "r"(en), "r"(0u) : "memory");
}
#endif  // HAVE_TCGEN05

// ---------------- GEMM: C = A[M,K] @ Bt[N,K]^T via tiled bf16 planes --------
// TN: output tile N (128 or 256); NS: ring depth. M tile fixed 128.
// R9 pipeline semantics: full-NS prologue, refill after own-commit wait.
// epi: 0 none, 1 relu, 2 add g_crow; transC: output transposed
template<int TN, int NS>
__global__ void __launch_bounds__(NTHR, 1)
gemm_bf(const bf16* __restrict__ Ah, const bf16* __restrict__ Al, int lda,
        const bf16* __restrict__ Bh, const bf16* __restrict__ Bl, int ldb,
        float* __restrict__ C, bf16* __restrict__ Ch, bf16* __restrict__ Cl,
        int ldc, int K, int epi, int transC)
{
    extern __shared__ char smem[];
    const int tid = threadIdx.x;
    const int col0 = blockIdx.x * TN;
    const int row0 = blockIdx.y * 128;

    constexpr int NBT = TN / 128;                       // B 128-row tiles per stage
    constexpr int STAGE_BYTES = 2 * PT_BYTES + 2 * NBT * PT_BYTES;

#if HAVE_TCGEN05
    const uint32_t smem_base = smem_to_u32(smem);
    const int wid = tid >> 5;
    const int lid = tid & 31;

    constexpr uint32_t IDESC =
        (1u << 4) | (1u << 7) | (1u << 10) | ((TN / 8) << 17) | ((128 / 16) << 24);

    if (wid == 0) TCGEN05_ALLOC(smem_base + 0, TN);
    if (tid == 0) {
#pragma unroll
        for (int s = 0; s < NS; ++s) {
            MBARRIER_INIT(MB_FULL(smem_base, s), 1);   // expect_tx arrive
            MBARRIER_INIT(MB_EMPTY(smem_base, s), 1);  // tcgen05.commit
        }
    }
    __syncthreads();
    uint32_t tmem;
    asm volatile("ld.shared.b32 %0, [%1];" : "=r"(tmem) : "r"(smem_base));

    const int nch = K / BKC;

    if (wid == 0 && elect_one_pred()) {
        auto load_chunk = [&](int n, int s) {
            uint32_t dst = smem_base + SM_HDR + s * STAGE_BYTES;
            uint32_t fb = MB_FULL(smem_base, s);
            MBARRIER_EXPECT_TX(fb, STAGE_BYTES);
            BULK_G2S(dst + 0 * PT_BYTES, Ah + pt_base(row0, n * BKC, lda), PT_BYTES, fb);
            BULK_G2S(dst + 1 * PT_BYTES, Al + pt_base(row0, n * BKC, lda), PT_BYTES, fb);
#pragma unroll
            for (int t = 0; t < NBT; ++t) {
                BULK_G2S(dst + (2 + t) * PT_BYTES,
                         Bh + pt_base(col0 + t * 128, n * BKC, ldb), PT_BYTES, fb);
                BULK_G2S(dst + (2 + NBT + t) * PT_BYTES,
                         Bl + pt_base(col0 + t * 128, n * BKC, ldb), PT_BYTES, fb);
            }
        };

        // full prologue: preload ALL NS stages (R9 semantics)
        const int P = (nch < NS) ? nch : NS;
        for (int p = 0; p < P; ++p) load_chunk(p, p);

        for (int c = 0; c < nch; ++c) {
            const int ci = c / NS;
            const int s  = c - ci * NS;
            MBARRIER_WAIT_PARITY(MB_FULL(smem_base, s), ci & 1);
            uint32_t stg = smem_base + SM_HDR + s * STAGE_BYTES;
            uint64_t ah = MAKE_SMEM_DESC(stg);
            uint64_t al = ah + (PT_BYTES >> 4);
            uint64_t bh = ah + 2 * (PT_BYTES >> 4);
            uint64_t bl = bh + NBT * (PT_BYTES >> 4);
            uint32_t en = (c > 0) ? 1u : 0u;
#pragma unroll
            for (int st = 0; st < 4; ++st) {     // 4 k-steps of 16 bf16
                mma_bf16(tmem, ah + 2 * st, bh + 2 * st, IDESC, en); en = 1u;
                mma_bf16(tmem, ah + 2 * st, bl + 2 * st, IDESC, 1u);
                mma_bf16(tmem, al + 2 * st, bh + 2 * st, IDESC, 1u);
            }
            TCGEN05_COMMIT(MB_EMPTY(smem_base, s));
            // refill: wait for this stage's own commit (chunk c done), then
            // load chunk c+NS into stage s (R9 semantics; lap-free).
            const int n = c + NS;
            if (n < nch) {
                MBARRIER_WAIT_PARITY(MB_EMPTY(smem_base, s), ci & 1);
                load_chunk(n, s);
            }
        }
        // final wait: lap-free ONLY for this thread.
        const int cl = nch - 1;
        MBARRIER_WAIT_PARITY(MB_EMPTY(smem_base, cl % NS), (cl / NS) & 1);
    }
    // rendezvous before epilogue
    __syncthreads();
    TCGEN05_FENCE_AFTER();

    // epilogue: 8 warps; warps 0-3 = first half of col groups, 4-7 = second half
    {
        constexpr int NGRP = TN / 32;
        constexpr int HALF = NGRP / 2;
        const int wg = wid >> 2;
        const int row = row0 + (wid & 3) * 32 + lid;
#pragma unroll
        for (int gg = 0; gg < HALF; ++gg) {
            const int g = wg * HALF + gg;
            uint32_t r[32];
            TCGEN05_LD_32X32B_X32(r, tmem + g * 32);
            TCGEN05_WAIT_LD();
            if (C) {
#pragma unroll
                for (int j = 0; j < 32; j += 4) {
                    const int col = col0 + g * 32 + j;
                    float v0 = __uint_as_float(r[j + 0]);
                    float v1 = __uint_as_float(r[j + 1]);
                    float v2 = __uint_as_float(r[j + 2]);
                    float v3 = __uint_as_float(r[j + 3]);
                    if (epi == 1) {
                        v0 = fmaxf(v0, 0.0f); v1 = fmaxf(v1, 0.0f);
                        v2 = fmaxf(v2, 0.0f); v3 = fmaxf(v3, 0.0f);
                    } else if (epi == 2) {
                        v0 += g_crow[col + 0]; v1 += g_crow[col + 1];
                        v2 += g_crow[col + 2]; v3 += g_crow[col + 3];
                    }
                    if (!transC) {
                        *(float4*)(C + (size_t)row * ldc + col) = make_float4(v0, v1, v2, v3);
                    } else {
                        C[(size_t)(col + 0) * ldc + row] = v0;
                        C[(size_t)(col + 1) * ldc + row] = v1;
                        C[(size_t)(col + 2) * ldc + row] = v2;
                        C[(size_t)(col + 3) * ldc + row] = v3;
                    }
                }
            }
            if (Ch) {
#pragma unroll
                for (int j = 0; j < 32; j += 8) {
                    const int colb = col0 + g * 32 + j;
                    float v[8];
#pragma unroll
                    for (int q = 0; q < 8; ++q) {
                        float t = __uint_as_float(r[j + q]);
                        if (epi == 1) t = fmaxf(t, 0.0f);
                        else if (epi == 2) t += g_crow[colb + q];
                        v[q] = t;
                    }
                    bf16 h[8], l[8];
#pragma unroll
                    for (int q = 0; q < 8; ++q) split_bf(v[q], h[q], l[q]);
                    if (!transC) {
                        size_t tb = pt_base(row, colb, ldc);
                        uint32_t sw = pt_sw(row & 127, colb & 63);
                        uint4 hq = make_uint4(pack2(h[0], h[1]), pack2(h[2], h[3]),
                                              pack2(h[4], h[5]), pack2(h[6], h[7]));
                        uint4 lq = make_uint4(pack2(l[0], l[1]), pack2(l[2], l[3]),
                                              pack2(l[4], l[5]), pack2(l[6], l[7]));
                        *(uint4*)((char*)(Ch + tb) + sw) = hq;
                        *(uint4*)((char*)(Cl + tb) + sw) = lq;
                    } else {
#pragma unroll
                        for (int q = 0; q < 8; ++q) {
                            const int col = colb + q;
                            size_t tb = pt_base(col, row, ldc);
                            uint32_t sw = pt_sw(col & 127, row & 63);
                            *(bf16*)((char*)(Ch + tb) + sw) = h[q];
                            *(bf16*)((char*)(Cl + tb) + sw) = l[q];
                        }
                    }
                }
            }
        }
    }
    __syncthreads();
    if (tid == 0) {
#pragma unroll
        for (int s = 0; s < NS; ++s) {
            asm volatile("mbarrier.inval.shared.b64 [%0];" :: "r"(MB_FULL(smem_base, s)) : "memory");
            asm volatile("mbarrier.inval.shared.b64 [%0];" :: "r"(MB_EMPTY(smem_base, s)) : "memory");
        }
    }
    __syncthreads();
    if (wid == 0) {
        TCGEN05_RELINQUISH();
        TCGEN05_DEALLOC(tmem, TN);
    }

#else
    // ------------- fallback (compile-only on non-103a passes) ---------------
    float* As = (float*)smem;                 // [16][128]
    float* Bs = As + 16 * 128;
    const int tx = tid & 15;
    const int ty = tid >> 4;

    auto rdp = [](const bf16* P, int r, int k, int Kl) {
        size_t tb = pt_base(r, k, Kl);
        uint32_t sw = pt_sw(r & 127, k & 63);
        return __bfloat162float(*(const bf16*)((const char*)(P + tb) + sw));
    };
    for (int cb = 0; cb < TN / 128; ++cb) {
        const int cbase = col0 + cb * 128;
        float acc[8][8];
#pragma unroll
        for (int i = 0; i < 8; i++)
#pragma unroll
            for (int j = 0; j < 8; j++) acc[i][j] = 0.0f;
        for (int k0 = 0; k0 < K; k0 += 16) {
            __syncthreads();
            for (int f = tid; f < 16 * 128; f += NTHR) {
                int kk = f >> 7, m = f & 127;
                As[kk * 128 + m] = rdp(Ah, row0 + m, k0 + kk, lda) + rdp(Al, row0 + m, k0 + kk, lda);
                Bs[kk * 128 + m] = rdp(Bh, cbase + m, k0 + kk, ldb) + rdp(Bl, cbase + m, k0 + kk, ldb);
            }
            __syncthreads();
#pragma unroll
            for (int kk = 0; kk < 16; kk++) {
                float a[8], b[8];
#pragma unroll
                for (int i = 0; i < 8; i++) a[i] = As[kk * 128 + ty * 8 + i];
#pragma unroll
                for (int j = 0; j < 8; j++) b[j] = Bs[kk * 128 + tx * 8 + j];
#pragma unroll
                for (int i = 0; i < 8; i++)
#pragma unroll
                    for (int j = 0; j < 8; j++) acc[i][j] = fmaf(a[i], b[j], acc[i][j]);
            }
        }
#pragma unroll
        for (int i = 0; i < 8; i++) {
            const int row = row0 + ty * 8 + i;
#pragma unroll
            for (int j = 0; j < 8; j++) {
                const int col = cbase + tx * 8 + j;
                float v = acc[i][j];
                if (epi == 1) v = fmaxf(v, 0.0f);
                else if (epi == 2) v += g_crow[col];
                if (C) {
                    size_t idx = transC ? ((size_t)col * ldc + row) : ((size_t)row * ldc + col);
                    C[idx] = v;
                }
                if (Ch) {
                    bf16 h, l; split_bf(v, h, l);
                    int pr = transC ? col : row;
                    int pk = transC ? row : col;
                    size_t tb = pt_base(pr, pk, ldc);
                    uint32_t sw = pt_sw(pr & 127, pk & 63);
                    *(bf16*)((char*)(Ch + tb) + sw) = h;
                    *(bf16*)((char*)(Cl + tb) + sw) = l;
                }
            }
        }
        __syncthreads();
    }
#endif
}

// ---------------- split kernels (write tiled plane layout) -------------------
__global__ void k_split_tiled(const float* __restrict__ src, bf16* __restrict__ dh,
                              bf16* __restrict__ dl, int R, int K) {
    size_t idx = (size_t)blockIdx.x * blockDim.x + threadIdx.x;
    size_t n8 = (size_t)K >> 3;
    if (idx >= (size_t)R * n8) return;
    int r = (int)(idx / n8);
    int k = (int)(idx % n8) * 8;
    float4 a = *(const float4*)(src + (size_t)r * K + k);
    float4 b = *(const float4*)(src + (size_t)r * K + k + 4);
    bf16 h[8], l[8];
    split_bf(a.x, h[0], l[0]); split_bf(a.y, h[1], l[1]);
    split_bf(a.z, h[2], l[2]); split_bf(a.w, h[3], l[3]);
    split_bf(b.x, h[4], l[4]); split_bf(b.y, h[5], l[5]);
    split_bf(b.z, h[6], l[6]); split_bf(b.w, h[7], l[7]);
    size_t tb = pt_base(r, k, K);
    uint32_t sw = pt_sw(r & 127, k & 63);
    *(uint4*)((char*)(dh + tb) + sw) = make_uint4(pack2(h[0], h[1]), pack2(h[2], h[3]),
                                                  pack2(h[4], h[5]), pack2(h[6], h[7]));
    *(uint4*)((char*)(dl + tb) + sw) = make_uint4(pack2(l[0], l[1]), pack2(l[2], l[3]),
                                                  pack2(l[4], l[5]), pack2(l[6], l[7]));
}

__global__ void k_split_T(const float* __restrict__ src, bf16* __restrict__ dh,
                          bf16* __restrict__ dl, int R, int K) {
    int idx = blockIdx.x * blockDim.x + threadIdx.x;
    int n8 = K >> 3;
    if (idx >= R * n8) return;
    int r = idx / n8;
    int k = (idx % n8) * 8;
    bf16 h[8], l[8];
#pragma unroll
    for (int q = 0; q < 8; ++q) split_bf(src[(size_t)(k + q) * R + r], h[q], l[q]);
    size_t tb = pt_base(r, k, K);
    uint32_t sw = pt_sw(r & 127, k & 63);
    *(uint4*)((char*)(dh + tb) + sw) = make_uint4(pack2(h[0], h[1]), pack2(h[2], h[3]),
                                                  pack2(h[4], h[5]), pack2(h[6], h[7]));
    *(uint4*)((char*)(dl + tb) + sw) = make_uint4(pack2(l[0], l[1]), pack2(l[2], l[3]),
                                                  pack2(l[4], l[5]), pack2(l[6], l[7]));
}

__global__ void k_split_wcatt(const float* __restrict__ W2, const float* __restrict__ W3,
                              const float* __restrict__ W4, const float* __restrict__ W5,
                              bf16* __restrict__ dh, bf16* __restrict__ dl) {
    int idx = blockIdx.x * blockDim.x + threadIdx.x;
    int n8 = H1D >> 3;
    if (idx >= WCATN * n8) return;
    int n = idx / n8;
    int k = (idx % n8) * 8;
    int sel = n >> 7, nn = n & (H2D - 1);
    const float* W = (sel == 0) ? W2 : (sel == 1) ? W3 : (sel == 2) ? W4 : W5;
    bf16 h[8], l[8];
#pragma unroll
    for (int q = 0; q < 8; ++q) split_bf(W[(size_t)(k + q) * H2D + nn], h[q], l[q]);
    size_t tb = pt_base(n, k, H1D);
    uint32_t sw = pt_sw(n & 127, k & 63);
    *(uint4*)((char*)(dh + tb) + sw) = make_uint4(pack2(h[0], h[1]), pack2(h[2], h[3]),
                                                  pack2(h[4], h[5]), pack2(h[6], h[7]));
    *(uint4*)((char*)(dl + tb) + sw) = make_uint4(pack2(l[0], l[1]), pack2(l[2], l[3]),
                                                  pack2(l[4], l[5]), pack2(l[6], l[7]));
}

__global__ void k_z(const float* __restrict__ Mb, const float* __restrict__ eps_z,
                    float* __restrict__ out_z, float* __restrict__ out_mu,
                    float* __restrict__ out_lv, bf16* __restrict__ zh,
                    bf16* __restrict__ zl) {
    int idx = blockIdx.x * blockDim.x + threadIdx.x;
    if (idx >= NN * (H2D / 8)) return;
    int i = idx / (H2D / 8);
    int j = (idx % (H2D / 8)) * 8;
    float4 mu0 = *(const float4*)(Mb + (size_t)i * WCATN + j);
    float4 mu1 = *(const float4*)(Mb + (size_t)i * WCATN + j + 4);
    float4 lv0 = *(const float4*)(Mb + (size_t)i * WCATN + H2D + j);
    float4 lv1 = *(const float4*)(Mb + (size_t)i * WCATN + H2D + j + 4);
    float4 e0 = *(const float4*)(eps_z + (size_t)i * H2D + j);
    float4 e1 = *(const float4*)(eps_z + (size_t)i * H2D + j + 4);
    *(float4*)(out_mu + (size_t)i * H2D + j) = mu0;
    *(float4*)(out_mu + (size_t)i * H2D + j + 4) = mu1;
    *(float4*)(out_lv + (size_t)i * H2D + j) = lv0;
    *(float4*)(out_lv + (size_t)i * H2D + j + 4) = lv1;
    float z[8];
    z[0] = e0.x * expf(lv0.x) + mu0.x; z[1] = e0.y * expf(lv0.y) + mu0.y;
    z[2] = e0.z * expf(lv0.z) + mu0.z; z[3] = e0.w * expf(lv0.w) + mu0.w;
    z[4] = e1.x * expf(lv1.x) + mu1.x; z[5] = e1.y * expf(lv1.y) + mu1.y;
    z[6] = e1.z * expf(lv1.z) + mu1.z; z[7] = e1.w * expf(lv1.w) + mu1.w;
    *(float4*)(out_z + (size_t)i * H2D + j) = make_float4(z[0], z[1], z[2], z[3]);
    *(float4*)(out_z + (size_t)i * H2D + j + 4) = make_float4(z[4], z[5], z[6], z[7]);
    bf16 h[8], l[8];
#pragma unroll
    for (int q = 0; q < 8; ++q) split_bf(z[q], h[q], l[q]);
    size_t tb = pt_base(i, j, H2D);
    uint32_t sw = pt_sw(i & 127, j & 63);
    *(uint4*)((char*)(zh + tb) + sw) = make_uint4(pack2(h[0], h[1]), pack2(h[2], h[3]),
                                                  pack2(h[4], h[5]), pack2(h[6], h[7]));
    *(uint4*)((char*)(zl + tb) + sw) = make_uint4(pack2(l[0], l[1]), pack2(l[2], l[3]),
                                                  pack2(l[4], l[5]), pack2(l[6], l[7]));
}

__global__ void k_reduce(const float* __restrict__ Mb) {
    __shared__ float s1[256];
    __shared__ float s2[256];
    int j = blockIdx.x, t = threadIdx.x;
    float a = 0.0f, b = 0.0f;
    for (int i = t; i < NN; i += 256) {
        float cm = Mb[(size_t)i * WCATN + 2 * H2D + j];
        float cl = Mb[(size_t)i * WCATN + 3 * H2D + j];
        float var = expf(cl);
        if (var == 0.0f) var = 1e-6f;
        float inv = 1.0f / var;
        a += inv;
        b += cm * inv;
    }
    s1[t] = a; s2[t] = b;
    __syncthreads();
    for (int s = 128; s > 0; s >>= 1) {
        if (t < s) { s1[t] += s1[t + s]; s2[t] += s2[t + s]; }
        __syncthreads();
    }
    if (t == 0) { g_prec[j] = s1[0]; g_wmu[j] = s2[0]; }
}

__global__ void k_final(const float* __restrict__ eps_g, const float* __restrict__ Wl,
                        const float* __restrict__ bl) {
    __shared__ float cl_sh[H2D];
    int j = threadIdx.x;
    float gvar = 1.0f / g_prec[j];
    float gmu = gvar * g_wmu[j];
    float gv = (gvar == 0.0f) ? 1e-6f : gvar;
    float glv = logf(gv);
    float cl = gmu + expf(0.5f * glv) * eps_g[j];
    g_gmu[j] = gmu;
    g_glv[j] = glv;
    cl_sh[j] = cl;
    __syncthreads();
    float s = bl[j];
#pragma unroll 8
    for (int k = 0; k < H2D; k++)
        s = fmaf(cl_sh[k], Wl[(H2D + k) * H2D + j], s);
    g_crow[j] = s;
}

__global__ void k_bcast(float* __restrict__ out_gmu, float* __restrict__ out_glv) {
    int idx = blockIdx.x * blockDim.x + threadIdx.x;
    if (idx >= NN * H2D) return;
    int j = idx & (H2D - 1);
    out_gmu[idx] = g_gmu[j];
    out_glv[idx] = g_glv[j];
}

// ---------------- launch ----------------------------------------------------
extern "C" void kernel_launch(void* const* d_in, const int* in_sizes, int n_in,
                              void* d_out, int out_size)
{
    const float* x     = (const float*)d_in[0];
    const float* adj   = (const float*)d_in[1];
    const float* W1    = (const float*)d_in[2];
    const float* W2    = (const float*)d_in[3];
    const float* W3    = (const float*)d_in[4];
    const float* W4    = (const float*)d_in[5];
    const float* W5    = (const float*)d_in[6];
    const float* Wl    = (const float*)d_in[7];
    const float* bl    = (const float*)d_in[8];
    const float* eps_z = (const float*)d_in[9];
    const float* eps_g = (const float*)d_in[10];

    float* out = (float*)d_out;
    float* out_recon = out;
    float* out_z     = out + (size_t)NN * NN;
    float* out_mu    = out_z  + (size_t)NN * H2D;
    float* out_lv    = out_mu + (size_t)NN * H2D;
    float* out_gmu   = out_lv + (size_t)NN * H2D;
    float* out_glv   = out_gmu + (size_t)NN * H2D;

    bf16 *adjh, *adjl, *xh, *xl, *W1th, *W1tl, *Wcatth, *Wcattl, *Wlth, *Wltl;
    bf16 *T0th, *T0tl, *h1h, *h1l, *T1th, *T1tl, *zh, *zl, *uzh, *uzl;
    float *Mb;
    cudaGetSymbolAddress((void**)&adjh,   g_adjh);
    cudaGetSymbolAddress((void**)&adjl,   g_adjl);
    cudaGetSymbolAddress((void**)&xh,     g_xh);
    cudaGetSymbolAddress((void**)&xl,     g_xl);
    cudaGetSymbolAddress((void**)&W1th,   g_W1th);
    cudaGetSymbolAddress((void**)&W1tl,   g_W1tl);
    cudaGetSymbolAddress((void**)&Wcatth, g_Wcatth);
    cudaGetSymbolAddress((void**)&Wcattl, g_Wcattl);
    cudaGetSymbolAddress((void**)&Wlth,   g_Wlth);
    cudaGetSymbolAddress((void**)&Wltl,   g_Wltl);
    cudaGetSymbolAddress((void**)&T0th,   g_T0th);
    cudaGetSymbolAddress((void**)&T0tl,   g_T0tl);
    cudaGetSymbolAddress((void**)&h1h,    g_h1h);
    cudaGetSymbolAddress((void**)&h1l,    g_h1l);
    cudaGetSymbolAddress((void**)&T1th,   g_T1th);
    cudaGetSymbolAddress((void**)&T1tl,   g_T1tl);
    cudaGetSymbolAddress((void**)&zh,     g_zh);
    cudaGetSymbolAddress((void**)&zl,     g_zl);
    cudaGetSymbolAddress((void**)&uzh,    g_uzh);
    cudaGetSymbolAddress((void**)&uzl,    g_uzl);
    cudaGetSymbolAddress((void**)&Mb,     g_Mb);

    const int SMEM128 = SM_HDR + 3 * (4 * PT_BYTES);   // 197632 B
    const int SMEM256 = SM_HDR + 2 * (6 * PT_BYTES);   // 197632 B
    cudaFuncSetAttribute(gemm_bf<128, 3>, cudaFuncAttributeMaxDynamicSharedMemorySize, SMEM128);
    cudaFuncSetAttribute(gemm_bf<256, 2>, cudaFuncAttributeMaxDynamicSharedMemorySize, SMEM256);

    // input splits (tiled plane layout)
    {
        size_t na = (size_t)NN * (NN / 8);
        k_split_tiled<<<(unsigned)((na + 255) / 256), 256>>>(adj, adjh, adjl, NN, NN);
        size_t nx = (size_t)NN * (F_IN / 8);
        k_split_tiled<<<(unsigned)((nx + 255) / 256), 256>>>(x, xh, xl, NN, F_IN);
        k_split_T<<<(H1D * F_IN / 8 + 255) / 256, 256>>>(W1, W1th, W1tl, H1D, F_IN);
        k_split_wcatt<<<(WCATN * H1D / 8 + 255) / 256, 256>>>(W2, W3, W4, W5, Wcatth, Wcattl);
        k_split_T<<<(H2D * H2D / 8 + 255) / 256, 256>>>(Wl, Wlth, Wltl, H2D, H2D);
    }

    // G1: T0t planes = (x @ W1)^T   M=8192 N=256 K=512
    gemm_bf<128, 3><<<dim3(H1D / 128, NN / 128), NTHR, SMEM128>>>(
        xh, xl, F_IN, W1th, W1tl, F_IN, nullptr, T0th, T0tl, NN, F_IN, 0, 1);
    // G2: h1 planes = relu(adj @ T0)  M=8192 N=256 K=8192
    gemm_bf<128, 3><<<dim3(H1D / 128, NN / 128), NTHR, SMEM128>>>(
        adjh, adjl, NN, T0th, T0tl, NN, nullptr, h1h, h1l, H1D, NN, 1, 0);
    // G3: T1t planes = (h1 @ Wcat)^T  M=8192 N=512 K=256
    gemm_bf<128, 3><<<dim3(WCATN / 128, NN / 128), NTHR, SMEM128>>>(
        h1h, h1l, H1D, Wcatth, Wcattl, H1D, nullptr, T1th, T1tl, NN, H1D, 0, 1);
    // G4: Mb = adj @ T1 (fp32)        M=8192 N=512 K=8192 (256-wide tiles)
    gemm_bf<256, 2><<<dim3(WCATN / 256, NN / 128), NTHR, SMEM256>>>(
        adjh, adjl, NN, T1th, T1tl, NN, Mb, nullptr, nullptr, WCATN, NN, 0, 0);

    // z / mu / logvar (+ z planes) + group evidence
    k_z     <<<(NN * (H2D / 8) + 255) / 256, 256>>>(Mb, eps_z, out_z, out_mu, out_lv, zh, zl);
    k_reduce<<<H2D, 256>>>(Mb);
    k_final <<<1, H2D>>>(eps_g, Wl, bl);
    k_bcast <<<(NN * H2D + 255) / 256, 256>>>(out_gmu, out_glv);

    // G5: uz planes = z @ Wl_top + crow   M=8192 N=128 K=128
    gemm_bf<128, 3><<<dim3(1, NN / 128), NTHR, SMEM128>>>(
        zh, zl, H2D, Wlth, Wltl, H2D, nullptr, uzh, uzl, H2D, H2D, 2, 0);
    // G6: recon = uz @ uz^T (fp32)        M=8192 N=8192 K=128
    gemm_bf<128, 3><<<dim3(NN / 128, NN / 128), NTHR, SMEM128>>>(
        uzh, uzl, H2D, uzh, uzl, H2D, out_recon, nullptr, nullptr, NN, H2D, 0, 0);
}

// round 13
// speedup vs baseline: 1.3703x; 1.1949x over previous
#include <cuda_runtime.h>
#include <cuda_bf16.h>
#include <cstdint>
#include <math.h>

// Problem sizes (fixed)
#define NN    8192
#define F_IN  512
#define H1D   256
#define H2D   128
#define WCATN 512   // 4*H2

typedef __nv_bfloat16 bf16;

// ---------------- scratch (device globals; no allocation allowed) -----------
// bf16 hi/lo planes stored TILED+SWIZZLED: logical [R][K] -> tiles (R/128)x(K/64),
// each tile 8192 bf16 = 16 KB contiguous, SW128-swizzled within.
// adj keeps ONLY the hi plane (lo-plane correction dropped; see R12 analysis).
__device__ bf16 g_adjh[(size_t)NN * NN];
__device__ bf16 g_xh[NN * F_IN];
__device__ bf16 g_xl[NN * F_IN];
__device__ bf16 g_W1th[H1D * F_IN];
__device__ bf16 g_W1tl[H1D * F_IN];
__device__ bf16 g_Wcatth[WCATN * H1D];
__device__ bf16 g_Wcattl[WCATN * H1D];
__device__ bf16 g_Wlth[H2D * H2D];
__device__ bf16 g_Wltl[H2D * H2D];
__device__ bf16 g_T0th[H1D * NN];
__device__ bf16 g_T0tl[H1D * NN];
__device__ bf16 g_h1h[NN * H1D];
__device__ bf16 g_h1l[NN * H1D];
__device__ bf16 g_T1th[WCATN * NN];
__device__ bf16 g_T1tl[WCATN * NN];
__device__ bf16 g_zh[NN * H2D];
__device__ bf16 g_zl[NN * H2D];
__device__ bf16 g_uzh[NN * H2D];
__device__ bf16 g_uzl[NN * H2D];
__device__ float g_Mb[NN * WCATN];
__device__ float g_prec[H2D];
__device__ float g_wmu[H2D];
__device__ float g_gmu[H2D];
__device__ float g_glv[H2D];
__device__ float g_crow[H2D];

// ---------------- common tile config ----------------------------------------
#define BKC        64
#define NTHR       256
#define SM_HDR     1024
#define PT_BYTES   16384                 // one stored 128x64 bf16 tile

#if defined(__CUDA_ARCH_FEAT_SM103_ALL) || defined(__CUDA_ARCH_FEAT_SM100_ALL)
#define HAVE_TCGEN05 1
#else
#define HAVE_TCGEN05 0
#endif

#define MB_FULL(base, s)  ((base) + 16 + 8 * (s))
#define MB_EMPTY(base, s) ((base) + 48 + 8 * (s))

// ---------------- tiled-plane addressing helpers -----------------------------
__host__ __device__ __forceinline__ size_t pt_base(int r, int k, int K) {
    return (((size_t)(r >> 7) * (size_t)(K >> 6)) + (size_t)(k >> 6)) << 13; // *8192
}
__device__ __forceinline__ uint32_t pt_sw(int rin, int kin) {
    uint32_t off = (uint32_t)(rin * 128 + kin * 2);
    return off ^ ((off >> 3) & 0x70);
}

__device__ __forceinline__ void split_bf(float v, bf16& h, bf16& l) {
    h = __float2bfloat16(v);
    l = __float2bfloat16(v - __bfloat162float(h));
}
__device__ __forceinline__ uint32_t pack2(bf16 a, bf16 b) {
    __nv_bfloat162 p = __halves2bfloat162(a, b);
    return *(uint32_t*)&p;
}
__device__ __forceinline__ uint32_t elect_one_pred() {
    uint32_t pred;
    asm volatile(
        "{\n\t.reg .pred p;\n\telect.sync _|p, 0xFFFFFFFF;\n\tselp.b32 %0, 1, 0, p;\n\t}"
        : "=r"(pred));
    return pred;
}
__device__ __forceinline__ uint32_t smem_to_u32(const void* smem_ptr) {
    uint32_t addr;
    asm("{ .reg .u64 tmp; cvta.to.shared.u64 tmp, %1; cvt.u32.u64 %0, tmp; }"
        : "=r"(addr) : "l"(smem_ptr));
    return addr;
}

#if HAVE_TCGEN05

#define MBARRIER_INIT(mbar, count) \
    asm volatile("mbarrier.init.shared.b64 [%0], %1;" \
        :: "r"((uint32_t)(mbar)), "r"((uint32_t)(count)) : "memory")
#define MBARRIER_EXPECT_TX(mbar, tx) \
    asm volatile("mbarrier.arrive.expect_tx.shared.b64 _, [%0], %1;" \
        :: "r"((uint32_t)(mbar)), "r"((uint32_t)(tx)) : "memory")
#define BULK_G2S(dst_smem, src_gmem, bytes, mbar) \
    asm volatile("cp.async.bulk.shared::cta.global.mbarrier::complete_tx::bytes " \
        "[%0], [%1], %2, [%3];" \
        :: "r"((uint32_t)(dst_smem)), "l"(src_gmem), "r"((uint32_t)(bytes)), \
           "r"((uint32_t)(mbar)) : "memory")
#define MBARRIER_WAIT_PARITY(mbar_smem_addr, phase_parity) do { \
    uint32_t _mbar = (uint32_t)(mbar_smem_addr); \
    uint32_t _parity = (uint32_t)(phase_parity); \
    uint32_t _done; \
    asm volatile( \
        "{\n\t.reg .pred p;\n\t" \
        "mbarrier.try_wait.parity.acquire.cta.shared::cta.b64 p, [%1], %2;\n\t" \
        "selp.b32 %0, 1, 0, p;\n\t}" \
        : "=r"(_done) : "r"(_mbar), "r"(_parity) : "memory"); \
    if (!_done) { \
        asm volatile( \
            "{\n\t.reg .pred P1;\n\t" \
            "WAIT_LOOP_%=:\n\t" \
            "mbarrier.try_wait.parity.acquire.cta.shared::cta.b64 P1, [%0], %1, 0x989680;\n\t" \
            "@P1 bra.uni WAIT_DONE_%=;\n\t" \
            "bra.uni WAIT_LOOP_%=;\n\t" \
            "WAIT_DONE_%=:\n\t}" \
            :: "r"(_mbar), "r"(_parity) : "memory"); \
    } \
} while(0)

#define TCGEN05_ALLOC(smem_result_addr, nCols) \
    asm volatile("tcgen05.alloc.cta_group::1.sync.aligned.shared::cta.b32 [%0], %1;" \
        :: "r"((uint32_t)(smem_result_addr)), "r"((uint32_t)(nCols)) : "memory")
#define TCGEN05_DEALLOC(tmem_addr, nCols) \
    asm volatile("tcgen05.dealloc.cta_group::1.sync.aligned.b32 %0, %1;" \
        :: "r"(tmem_addr), "r"((uint32_t)(nCols)))
#define TCGEN05_RELINQUISH() \
    asm volatile("tcgen05.relinquish_alloc_permit.cta_group::1.sync.aligned;")
#define TCGEN05_COMMIT(mbar_smem_addr) \
    asm volatile("tcgen05.commit.cta_group::1.mbarrier::arrive::one.shared::cluster.b64 [%0];" \
        :: "r"((uint32_t)(mbar_smem_addr)) : "memory")
#define TCGEN05_WAIT_LD() \
    asm volatile("tcgen05.wait::ld.sync.aligned;" ::: "memory")
#define TCGEN05_FENCE_AFTER() \
    asm volatile("tcgen05.fence::after_thread_sync;" ::: "memory")

#define TCGEN05_LD_32X32B_X32(r, tmem_addr) \
    asm volatile( \
        "tcgen05.ld.sync.aligned.32x32b.x32.b32 " \
        "{%0, %1, %2, %3, %4, %5, %6, %7, " \
        " %8, %9, %10, %11, %12, %13, %14, %15, " \
        " %16, %17, %18, %19, %20, %21, %22, %23, " \
        " %24, %25, %26, %27, %28, %29, %30, %31}, [%32];" \
        : "=r"((r)[0]),  "=r"((r)[1]),  "=r"((r)[2]),  "=r"((r)[3]), \
          "=r"((r)[4]),  "=r"((r)[5]),  "=r"((r)[6]),  "=r"((r)[7]), \
          "=r"((r)[8]),  "=r"((r)[9]),  "=r"((r)[10]), "=r"((r)[11]), \
          "=r"((r)[12]), "=r"((r)[13]), "=r"((r)[14]), "=r"((r)[15]), \
          "=r"((r)[16]), "=r"((r)[17]), "=r"((r)[18]), "=r"((r)[19]), \
          "=r"((r)[20]), "=r"((r)[21]), "=r"((r)[22]), "=r"((r)[23]), \
          "=r"((r)[24]), "=r"((r)[25]), "=r"((r)[26]), "=r"((r)[27]), \
          "=r"((r)[28]), "=r"((r)[29]), "=r"((r)[30]), "=r"((r)[31]) \
        : "r"(tmem_addr))

static constexpr uint64_t SMEM_DESC_BASE_SW128 =
    (uint64_t(2)  << 61) | (uint64_t(1) << 46) | (uint64_t(64) << 32) | (uint64_t(1) << 16);
#define MAKE_SMEM_DESC(base_addr) \
    (SMEM_DESC_BASE_SW128 | ((uint64_t)((base_addr) >> 4) & 0x3FFF))

__device__ __forceinline__ void mma_bf16(uint32_t d, uint64_t ad, uint64_t bd,
                                         uint32_t idesc, uint32_t en) {
    asm volatile(
        "{\n\t.reg .pred p;\n\tsetp.ne.u32 p, %4, 0;\n\t"
        "tcgen05.mma.cta_group::1.kind::f16 [%0], %1, %2, %3, {%5,%5,%5,%5}, p;\n\t}"
        :: "r"(d), "l"(ad), "l"(bd), "r"(idesc), "r"(en), "r"(0u) : "memory");
}
#endif  // HAVE_TCGEN05

// ---------------- GEMM: C = A[M,K] @ Bt[N,K]^T via tiled bf16 planes --------
// TN: output tile N; NS: ring depth; HAL: A has a lo plane. M tile fixed 128.
// Pipeline: full-NS prologue, refill after own-commit wait (R9/R11 semantics).
// epi: 0 none, 1 relu, 2 add g_crow; transC: output transposed
template<int TN, int NS, bool HAL>
__global__ void __launch_bounds__(NTHR, 1)
gemm_bf(const bf16* __restrict__ Ah, const bf16* __restrict__ Al, int lda,
        const bf16* __restrict__ Bh, const bf16* __restrict__ Bl, int ldb,
        float* __restrict__ C, bf16* __restrict__ Ch, bf16* __restrict__ Cl,
        int ldc, int K, int epi, int transC)
{
    extern __shared__ char smem[];
    const int tid = threadIdx.x;
    const int col0 = blockIdx.x * TN;
    const int row0 = blockIdx.y * 128;

    constexpr int NBT = TN / 128;                      // B 128-row tiles per stage
    constexpr int ATL = HAL ? 2 : 1;                   // A tiles per stage
    constexpr int STAGE_BYTES = (ATL + 2 * NBT) * PT_BYTES;

#if HAVE_TCGEN05
    const uint32_t smem_base = smem_to_u32(smem);
    const int wid = tid >> 5;
    const int lid = tid & 31;

    constexpr uint32_t IDESC =
        (1u << 4) | (1u << 7) | (1u << 10) | ((TN / 8) << 17) | ((128 / 16) << 24);

    if (wid == 0) TCGEN05_ALLOC(smem_base + 0, TN);
    if (tid == 0) {
#pragma unroll
        for (int s = 0; s < NS; ++s) {
            MBARRIER_INIT(MB_FULL(smem_base, s), 1);   // expect_tx arrive
            MBARRIER_INIT(MB_EMPTY(smem_base, s), 1);  // tcgen05.commit
        }
    }
    __syncthreads();
    uint32_t tmem;
    asm volatile("ld.shared.b32 %0, [%1];" : "=r"(tmem) : "r"(smem_base));

    const int nch = K / BKC;

    if (wid == 0 && elect_one_pred()) {
        auto load_chunk = [&](int n, int s) {
            uint32_t dst = smem_base + SM_HDR + s * STAGE_BYTES;
            uint32_t fb = MB_FULL(smem_base, s);
            MBARRIER_EXPECT_TX(fb, STAGE_BYTES);
            BULK_G2S(dst, Ah + pt_base(row0, n * BKC, lda), PT_BYTES, fb);
            if (HAL)
                BULK_G2S(dst + PT_BYTES, Al + pt_base(row0, n * BKC, lda), PT_BYTES, fb);
#pragma unroll
            for (int t = 0; t < NBT; ++t) {
                BULK_G2S(dst + (ATL + t) * PT_BYTES,
                         Bh + pt_base(col0 + t * 128, n * BKC, ldb), PT_BYTES, fb);
                BULK_G2S(dst + (ATL + NBT + t) * PT_BYTES,
                         Bl + pt_base(col0 + t * 128, n * BKC, ldb), PT_BYTES, fb);
            }
        };

        // full prologue: preload ALL NS stages
        const int P = (nch < NS) ? nch : NS;
        for (int p = 0; p < P; ++p) load_chunk(p, p);

        for (int c = 0; c < nch; ++c) {
            const int ci = c / NS;
            const int s  = c - ci * NS;
            MBARRIER_WAIT_PARITY(MB_FULL(smem_base, s), ci & 1);
            uint32_t stg = smem_base + SM_HDR + s * STAGE_BYTES;
            uint64_t ah = MAKE_SMEM_DESC(stg);
            uint64_t al = ah + (PT_BYTES >> 4);
            uint64_t bh = ah + ATL * (PT_BYTES >> 4);
            uint64_t bl = bh + NBT * (PT_BYTES >> 4);
            uint32_t en = (c > 0) ? 1u : 0u;
#pragma unroll
            for (int st = 0; st < 4; ++st) {     // 4 k-steps of 16 bf16
                mma_bf16(tmem, ah + 2 * st, bh + 2 * st, IDESC, en); en = 1u;
                mma_bf16(tmem, ah + 2 * st, bl + 2 * st, IDESC, 1u);
                if (HAL) mma_bf16(tmem, al + 2 * st, bh + 2 * st, IDESC, 1u);
            }
            TCGEN05_COMMIT(MB_EMPTY(smem_base, s));
            // refill this stage with chunk c+NS once chunk c's MMAs are done
            const int n = c + NS;
            if (n < nch) {
                MBARRIER_WAIT_PARITY(MB_EMPTY(smem_base, s), ci & 1);
                load_chunk(n, s);
            }
        }
        // final wait: lap-free ONLY for this thread.
        const int cl = nch - 1;
        MBARRIER_WAIT_PARITY(MB_EMPTY(smem_base, cl % NS), (cl / NS) & 1);
    }
    // rendezvous before epilogue
    __syncthreads();
    TCGEN05_FENCE_AFTER();

    // epilogue: 8 warps; warps 0-3 = first half of col groups, 4-7 = second half
    {
        constexpr int NGRP = TN / 32;
        constexpr int HALF = NGRP / 2;
        const int wg = wid >> 2;
        const int row = row0 + (wid & 3) * 32 + lid;
#pragma unroll
        for (int gg = 0; gg < HALF; ++gg) {
            const int g = wg * HALF + gg;
            uint32_t r[32];
            TCGEN05_LD_32X32B_X32(r, tmem + g * 32);
            TCGEN05_WAIT_LD();
            if (C) {
#pragma unroll
                for (int j = 0; j < 32; j += 4) {
                    const int col = col0 + g * 32 + j;
                    float v0 = __uint_as_float(r[j + 0]);
                    float v1 = __uint_as_float(r[j + 1]);
                    float v2 = __uint_as_float(r[j + 2]);
                    float v3 = __uint_as_float(r[j + 3]);
                    if (epi == 1) {
                        v0 = fmaxf(v0, 0.0f); v1 = fmaxf(v1, 0.0f);
                        v2 = fmaxf(v2, 0.0f); v3 = fmaxf(v3, 0.0f);
                    } else if (epi == 2) {
                        v0 += g_crow[col + 0]; v1 += g_crow[col + 1];
                        v2 += g_crow[col + 2]; v3 += g_crow[col + 3];
                    }
                    if (!transC) {
                        *(float4*)(C + (size_t)row * ldc + col) = make_float4(v0, v1, v2, v3);
                    } else {
                        C[(size_t)(col + 0) * ldc + row] = v0;
                        C[(size_t)(col + 1) * ldc + row] = v1;
                        C[(size_t)(col + 2) * ldc + row] = v2;
                        C[(size_t)(col + 3) * ldc + row] = v3;
                    }
                }
            }
            if (Ch) {
#pragma unroll
                for (int j = 0; j < 32; j += 8) {
                    const int colb = col0 + g * 32 + j;
                    float v[8];
#pragma unroll
                    for (int q = 0; q < 8; ++q) {
                        float t = __uint_as_float(r[j + q]);
                        if (epi == 1) t = fmaxf(t, 0.0f);
                        else if (epi == 2) t += g_crow[colb + q];
                        v[q] = t;
                    }
                    bf16 h[8], l[8];
#pragma unroll
                    for (int q = 0; q < 8; ++q) split_bf(v[q], h[q], l[q]);
                    if (!transC) {
                        size_t tb = pt_base(row, colb, ldc);
                        uint32_t sw = pt_sw(row & 127, colb & 63);
                        uint4 hq = make_uint4(pack2(h[0], h[1]), pack2(h[2], h[3]),
                                              pack2(h[4], h[5]), pack2(h[6], h[7]));
                        uint4 lq = make_uint4(pack2(l[0], l[1]), pack2(l[2], l[3]),
                                              pack2(l[4], l[5]), pack2(l[6], l[7]));
                        *(uint4*)((char*)(Ch + tb) + sw) = hq;
                        *(uint4*)((char*)(Cl + tb) + sw) = lq;
                    } else {
#pragma unroll
                        for (int q = 0; q < 8; ++q) {
                            const int col = colb + q;
                            size_t tb = pt_base(col, row, ldc);
                            uint32_t sw = pt_sw(col & 127, row & 63);
                            *(bf16*)((char*)(Ch + tb) + sw) = h[q];
                            *(bf16*)((char*)(Cl + tb) + sw) = l[q];
                        }
                    }
                }
            }
        }
    }
    __syncthreads();
    if (tid == 0) {
#pragma unroll
        for (int s = 0; s < NS; ++s) {
            asm volatile("mbarrier.inval.shared.b64 [%0];" :: "r"(MB_FULL(smem_base, s)) : "memory");
            asm volatile("mbarrier.inval.shared.b64 [%0];" :: "r"(MB_EMPTY(smem_base, s)) : "memory");
        }
    }
    __syncthreads();
    if (wid == 0) {
        TCGEN05_RELINQUISH();
        TCGEN05_DEALLOC(tmem, TN);
    }

#else
    // ------------- fallback (compile-only on non-103a passes) ---------------
    float* As = (float*)smem;                 // [16][128]
    float* Bs = As + 16 * 128;
    const int tx = tid & 15;
    const int ty = tid >> 4;

    auto rdp = [](const bf16* P, int r, int k, int Kl) {
        size_t tb = pt_base(r, k, Kl);
        uint32_t sw = pt_sw(r & 127, k & 63);
        return __bfloat162float(*(const bf16*)((const char*)(P + tb) + sw));
    };
    for (int cb = 0; cb < TN / 128; ++cb) {
        const int cbase = col0 + cb * 128;
        float acc[8][8];
#pragma unroll
        for (int i = 0; i < 8; i++)
#pragma unroll
            for (int j = 0; j < 8; j++) acc[i][j] = 0.0f;
        for (int k0 = 0; k0 < K; k0 += 16) {
            __syncthreads();
            for (int f = tid; f < 16 * 128; f += NTHR) {
                int kk = f >> 7, m = f & 127;
                float av = rdp(Ah, row0 + m, k0 + kk, lda);
                if (HAL) av += rdp(Al, row0 + m, k0 + kk, lda);
                As[kk * 128 + m] = av;
                Bs[kk * 128 + m] = rdp(Bh, cbase + m, k0 + kk, ldb) + rdp(Bl, cbase + m, k0 + kk, ldb);
            }
            __syncthreads();
#pragma unroll
            for (int kk = 0; kk < 16; kk++) {
                float a[8], b[8];
#pragma unroll
                for (int i = 0; i < 8; i++) a[i] = As[kk * 128 + ty * 8 + i];
#pragma unroll
                for (int j = 0; j < 8; j++) b[j] = Bs[kk * 128 + tx * 8 + j];
#pragma unroll
                for (int i = 0; i < 8; i++)
#pragma unroll
                    for (int j = 0; j < 8; j++) acc[i][j] = fmaf(a[i], b[j], acc[i][j]);
            }
        }
#pragma unroll
        for (int i = 0; i < 8; i++) {
            const int row = row0 + ty * 8 + i;
#pragma unroll
            for (int j = 0; j < 8; j++) {
                const int col = cbase + tx * 8 + j;
                float v = acc[i][j];
                if (epi == 1) v = fmaxf(v, 0.0f);
                else if (epi == 2) v += g_crow[col];
                if (C) {
                    size_t idx = transC ? ((size_t)col * ldc + row) : ((size_t)row * ldc + col);
                    C[idx] = v;
                }
                if (Ch) {
                    bf16 h, l; split_bf(v, h, l);
                    int pr = transC ? col : row;
                    int pk = transC ? row : col;
                    size_t tb = pt_base(pr, pk, ldc);
                    uint32_t sw = pt_sw(pr & 127, pk & 63);
                    *(bf16*)((char*)(Ch + tb) + sw) = h;
                    *(bf16*)((char*)(Cl + tb) + sw) = l;
                }
            }
        }
        __syncthreads();
    }
#endif
}

// ---------------- split kernels (write tiled plane layout) -------------------
// hi-only split (for adj)
__global__ void k_split_h(const float* __restrict__ src, bf16* __restrict__ dh,
                          int R, int K) {
    size_t idx = (size_t)blockIdx.x * blockDim.x + threadIdx.x;
    size_t n8 = (size_t)K >> 3;
    if (idx >= (size_t)R * n8) return;
    int r = (int)(idx / n8);
    int k = (int)(idx % n8) * 8;
    float4 a = *(const float4*)(src + (size_t)r * K + k);
    float4 b = *(const float4*)(src + (size_t)r * K + k + 4);
    bf16 h[8];
    h[0] = __float2bfloat16(a.x); h[1] = __float2bfloat16(a.y);
    h[2] = __float2bfloat16(a.z); h[3] = __float2bfloat16(a.w);
    h[4] = __float2bfloat16(b.x); h[5] = __float2bfloat16(b.y);
    h[6] = __float2bfloat16(b.z); h[7] = __float2bfloat16(b.w);
    size_t tb = pt_base(r, k, K);
    uint32_t sw = pt_sw(r & 127, k & 63);
    *(uint4*)((char*)(dh + tb) + sw) = make_uint4(pack2(h[0], h[1]), pack2(h[2], h[3]),
                                                  pack2(h[4], h[5]), pack2(h[6], h[7]));
}

__global__ void k_split_tiled(const float* __restrict__ src, bf16* __restrict__ dh,
                              bf16* __restrict__ dl, int R, int K) {
    size_t idx = (size_t)blockIdx.x * blockDim.x + threadIdx.x;
    size_t n8 = (size_t)K >> 3;
    if (idx >= (size_t)R * n8) return;
    int r = (int)(idx / n8);
    int k = (int)(idx % n8) * 8;
    float4 a = *(const float4*)(src + (size_t)r * K + k);
    float4 b = *(const float4*)(src + (size_t)r * K + k + 4);
    bf16 h[8], l[8];
    split_bf(a.x, h[0], l[0]); split_bf(a.y, h[1], l[1]);
    split_bf(a.z, h[2], l[2]); split_bf(a.w, h[3], l[3]);
    split_bf(b.x, h[4], l[4]); split_bf(b.y, h[5], l[5]);
    split_bf(b.z, h[6], l[6]); split_bf(b.w, h[7], l[7]);
    size_t tb = pt_base(r, k, K);
    uint32_t sw = pt_sw(r & 127, k & 63);
    *(uint4*)((char*)(dh + tb) + sw) = make_uint4(pack2(h[0], h[1]), pack2(h[2], h[3]),
                                                  pack2(h[4], h[5]), pack2(h[6], h[7]));
    *(uint4*)((char*)(dl + tb) + sw) = make_uint4(pack2(l[0], l[1]), pack2(l[2], l[3]),
                                                  pack2(l[4], l[5]), pack2(l[6], l[7]));
}

__global__ void k_split_T(const float* __restrict__ src, bf16* __restrict__ dh,
                          bf16* __restrict__ dl, int R, int K) {
    int idx = blockIdx.x * blockDim.x + threadIdx.x;
    int n8 = K >> 3;
    if (idx >= R * n8) return;
    int r = idx / n8;
    int k = (idx % n8) * 8;
    bf16 h[8], l[8];
#pragma unroll
    for (int q = 0; q < 8; ++q) split_bf(src[(size_t)(k + q) * R + r], h[q], l[q]);
    size_t tb = pt_base(r, k, K);
    uint32_t sw = pt_sw(r & 127, k & 63);
    *(uint4*)((char*)(dh + tb) + sw) = make_uint4(pack2(h[0], h[1]), pack2(h[2], h[3]),
                                                  pack2(h[4], h[5]), pack2(h[6], h[7]));
    *(uint4*)((char*)(dl + tb) + sw) = make_uint4(pack2(l[0], l[1]), pack2(l[2], l[3]),
                                                  pack2(l[4], l[5]), pack2(l[6], l[7]));
}

__global__ void k_split_wcatt(const float* __restrict__ W2, const float* __restrict__ W3,
                              const float* __restrict__ W4, const float* __restrict__ W5,
                              bf16* __restrict__ dh, bf16* __restrict__ dl) {
    int idx = blockIdx.x * blockDim.x + threadIdx.x;
    int n8 = H1D >> 3;
    if (idx >= WCATN * n8) return;
    int n = idx / n8;
    int k = (idx % n8) * 8;
    int sel = n >> 7, nn = n & (H2D - 1);
    const float* W = (sel == 0) ? W2 : (sel == 1) ? W3 : (sel == 2) ? W4 : W5;
    bf16 h[8], l[8];
#pragma unroll
    for (int q = 0; q < 8; ++q) split_bf(W[(size_t)(k + q) * H2D + nn], h[q], l[q]);
    size_t tb = pt_base(n, k, H1D);
    uint32_t sw = pt_sw(n & 127, k & 63);
    *(uint4*)((char*)(dh + tb) + sw) = make_uint4(pack2(h[0], h[1]), pack2(h[2], h[3]),
                                                  pack2(h[4], h[5]), pack2(h[6], h[7]));
    *(uint4*)((char*)(dl + tb) + sw) = make_uint4(pack2(l[0], l[1]), pack2(l[2], l[3]),
                                                  pack2(l[4], l[5]), pack2(l[6], l[7]));
}

__global__ void k_z(const float* __restrict__ Mb, const float* __restrict__ eps_z,
                    float* __restrict__ out_z, float* __restrict__ out_mu,
                    float* __restrict__ out_lv, bf16* __restrict__ zh,
                    bf16* __restrict__ zl) {
    int idx = blockIdx.x * blockDim.x + threadIdx.x;
    if (idx >= NN * (H2D / 8)) return;
    int i = idx / (H2D / 8);
    int j = (idx % (H2D / 8)) * 8;
    float4 mu0 = *(const float4*)(Mb + (size_t)i * WCATN + j);
    float4 mu1 = *(const float4*)(Mb + (size_t)i * WCATN + j + 4);
    float4 lv0 = *(const float4*)(Mb + (size_t)i * WCATN + H2D + j);
    float4 lv1 = *(const float4*)(Mb + (size_t)i * WCATN + H2D + j + 4);
    float4 e0 = *(const float4*)(eps_z + (size_t)i * H2D + j);
    float4 e1 = *(const float4*)(eps_z + (size_t)i * H2D + j + 4);
    *(float4*)(out_mu + (size_t)i * H2D + j) = mu0;
    *(float4*)(out_mu + (size_t)i * H2D + j + 4) = mu1;
    *(float4*)(out_lv + (size_t)i * H2D + j) = lv0;
    *(float4*)(out_lv + (size_t)i * H2D + j + 4) = lv1;
    float z[8];
    z[0] = e0.x * expf(lv0.x) + mu0.x; z[1] = e0.y * expf(lv0.y) + mu0.y;
    z[2] = e0.z * expf(lv0.z) + mu0.z; z[3] = e0.w * expf(lv0.w) + mu0.w;
    z[4] = e1.x * expf(lv1.x) + mu1.x; z[5] = e1.y * expf(lv1.y) + mu1.y;
    z[6] = e1.z * expf(lv1.z) + mu1.z; z[7] = e1.w * expf(lv1.w) + mu1.w;
    *(float4*)(out_z + (size_t)i * H2D + j) = make_float4(z[0], z[1], z[2], z[3]);
    *(float4*)(out_z + (size_t)i * H2D + j + 4) = make_float4(z[4], z[5], z[6], z[7]);
    bf16 h[8], l[8];
#pragma unroll
    for (int q = 0; q < 8; ++q) split_bf(z[q], h[q], l[q]);
    size_t tb = pt_base(i, j, H2D);
    uint32_t sw = pt_sw(i & 127, j & 63);
    *(uint4*)((char*)(zh + tb) + sw) = make_uint4(pack2(h[0], h[1]), pack2(h[2], h[3]),
                                                  pack2(h[4], h[5]), pack2(h[6], h[7]));
    *(uint4*)((char*)(zl + tb) + sw) = make_uint4(pack2(l[0], l[1]), pack2(l[2], l[3]),
                                                  pack2(l[4], l[5]), pack2(l[6], l[7]));
}

__global__ void k_reduce(const float* __restrict__ Mb) {
    __shared__ float s1[256];
    __shared__ float s2[256];
    int j = blockIdx.x, t = threadIdx.x;
    float a = 0.0f, b = 0.0f;
    for (int i = t; i < NN; i += 256) {
        float cm = Mb[(size_t)i * WCATN + 2 * H2D + j];
        float cl = Mb[(size_t)i * WCATN + 3 * H2D + j];
        float var = expf(cl);
        if (var == 0.0f) var = 1e-6f;
        float inv = 1.0f / var;
        a += inv;
        b += cm * inv;
    }
    s1[t] = a; s2[t] = b;
    __syncthreads();
    for (int s = 128; s > 0; s >>= 1) {
        if (t < s) { s1[t] += s1[t + s]; s2[t] += s2[t + s]; }
        __syncthreads();
    }
    if (t == 0) { g_prec[j] = s1[0]; g_wmu[j] = s2[0]; }
}

__global__ void k_final(const float* __restrict__ eps_g, const float* __restrict__ Wl,
                        const float* __restrict__ bl) {
    __shared__ float cl_sh[H2D];
    int j = threadIdx.x;
    float gvar = 1.0f / g_prec[j];
    float gmu = gvar * g_wmu[j];
    float gv = (gvar == 0.0f) ? 1e-6f : gvar;
    float glv = logf(gv);
    float cl = gmu + expf(0.5f * glv) * eps_g[j];
    g_gmu[j] = gmu;
    g_glv[j] = glv;
    cl_sh[j] = cl;
    __syncthreads();
    float s = bl[j];
#pragma unroll 8
    for (int k = 0; k < H2D; k++)
        s = fmaf(cl_sh[k], Wl[(H2D + k) * H2D + j], s);
    g_crow[j] = s;
}

__global__ void k_bcast(float* __restrict__ out_gmu, float* __restrict__ out_glv) {
    int idx = blockIdx.x * blockDim.x + threadIdx.x;
    if (idx >= NN * H2D) return;
    int j = idx & (H2D - 1);
    out_gmu[idx] = g_gmu[j];
    out_glv[idx] = g_glv[j];
}

// ---------------- launch ----------------------------------------------------
extern "C" void kernel_launch(void* const* d_in, const int* in_sizes, int n_in,
                              void* d_out, int out_size)
{
    const float* x     = (const float*)d_in[0];
    const float* adj   = (const float*)d_in[1];
    const float* W1    = (const float*)d_in[2];
    const float* W2    = (const float*)d_in[3];
    const float* W3    = (const float*)d_in[4];
    const float* W4    = (const float*)d_in[5];
    const float* W5    = (const float*)d_in[6];
    const float* Wl    = (const float*)d_in[7];
    const float* bl    = (const float*)d_in[8];
    const float* eps_z = (const float*)d_in[9];
    const float* eps_g = (const float*)d_in[10];

    float* out = (float*)d_out;
    float* out_recon = out;
    float* out_z     = out + (size_t)NN * NN;
    float* out_mu    = out_z  + (size_t)NN * H2D;
    float* out_lv    = out_mu + (size_t)NN * H2D;
    float* out_gmu   = out_lv + (size_t)NN * H2D;
    float* out_glv   = out_gmu + (size_t)NN * H2D;

    bf16 *adjh, *xh, *xl, *W1th, *W1tl, *Wcatth, *Wcattl, *Wlth, *Wltl;
    bf16 *T0th, *T0tl, *h1h, *h1l, *T1th, *T1tl, *zh, *zl, *uzh, *uzl;
    float *Mb;
    cudaGetSymbolAddress((void**)&adjh,   g_adjh);
    cudaGetSymbolAddress((void**)&xh,     g_xh);
    cudaGetSymbolAddress((void**)&xl,     g_xl);
    cudaGetSymbolAddress((void**)&W1th,   g_W1th);
    cudaGetSymbolAddress((void**)&W1tl,   g_W1tl);
    cudaGetSymbolAddress((void**)&Wcatth, g_Wcatth);
    cudaGetSymbolAddress((void**)&Wcattl, g_Wcattl);
    cudaGetSymbolAddress((void**)&Wlth,   g_Wlth);
    cudaGetSymbolAddress((void**)&Wltl,   g_Wltl);
    cudaGetSymbolAddress((void**)&T0th,   g_T0th);
    cudaGetSymbolAddress((void**)&T0tl,   g_T0tl);
    cudaGetSymbolAddress((void**)&h1h,    g_h1h);
    cudaGetSymbolAddress((void**)&h1l,    g_h1l);
    cudaGetSymbolAddress((void**)&T1th,   g_T1th);
    cudaGetSymbolAddress((void**)&T1tl,   g_T1tl);
    cudaGetSymbolAddress((void**)&zh,     g_zh);
    cudaGetSymbolAddress((void**)&zl,     g_zl);
    cudaGetSymbolAddress((void**)&uzh,    g_uzh);
    cudaGetSymbolAddress((void**)&uzl,    g_uzl);
    cudaGetSymbolAddress((void**)&Mb,     g_Mb);

    const int SMEM_G1  = SM_HDR + 3 * 4 * PT_BYTES;  // <128,3,true>: 197632
    const int SMEM_G2  = SM_HDR + 4 * 3 * PT_BYTES;  // <128,4,false>: 197632
    const int SMEM_G4  = SM_HDR + 2 * 5 * PT_BYTES;  // <256,2,false>: 164864
    const int SMEM_G6  = SM_HDR + 2 * 6 * PT_BYTES;  // <256,2,true>: 197632
    cudaFuncSetAttribute(gemm_bf<128, 3, true>,  cudaFuncAttributeMaxDynamicSharedMemorySize, SMEM_G1);
    cudaFuncSetAttribute(gemm_bf<128, 4, false>, cudaFuncAttributeMaxDynamicSharedMemorySize, SMEM_G2);
    cudaFuncSetAttribute(gemm_bf<256, 2, false>, cudaFuncAttributeMaxDynamicSharedMemorySize, SMEM_G4);
    cudaFuncSetAttribute(gemm_bf<256, 2, true>,  cudaFuncAttributeMaxDynamicSharedMemorySize, SMEM_G6);

    // input splits (tiled plane layout); adj = hi only
    {
        size_t na = (size_t)NN * (NN / 8);
        k_split_h<<<(unsigned)((na + 255) / 256), 256>>>(adj, adjh, NN, NN);
        size_t nx = (size_t)NN * (F_IN / 8);
        k_split_tiled<<<(unsigned)((nx + 255) / 256), 256>>>(x, xh, xl, NN, F_IN);
        k_split_T<<<(H1D * F_IN / 8 + 255) / 256, 256>>>(W1, W1th, W1tl, H1D, F_IN);
        k_split_wcatt<<<(WCATN * H1D / 8 + 255) / 256, 256>>>(W2, W3, W4, W5, Wcatth, Wcattl);
        k_split_T<<<(H2D * H2D / 8 + 255) / 256, 256>>>(Wl, Wlth, Wltl, H2D, H2D);
    }

    // G1: T0t planes = (x @ W1)^T   M=8192 N=256 K=512
    gemm_bf<128, 3, true><<<dim3(H1D / 128, NN / 128), NTHR, SMEM_G1>>>(
        xh, xl, F_IN, W1th, W1tl, F_IN, nullptr, T0th, T0tl, NN, F_IN, 0, 1);
    // G2: h1 planes = relu(adj @ T0)  M=8192 N=256 K=8192 (adj hi-only, NS=4)
    gemm_bf<128, 4, false><<<dim3(H1D / 128, NN / 128), NTHR, SMEM_G2>>>(
        adjh, adjh, NN, T0th, T0tl, NN, nullptr, h1h, h1l, H1D, NN, 1, 0);
    // G3: T1t planes = (h1 @ Wcat)^T  M=8192 N=512 K=256
    gemm_bf<128, 3, true><<<dim3(WCATN / 128, NN / 128), NTHR, SMEM_G1>>>(
        h1h, h1l, H1D, Wcatth, Wcattl, H1D, nullptr, T1th, T1tl, NN, H1D, 0, 1);
    // G4: Mb = adj @ T1 (fp32)        M=8192 N=512 K=8192 (adj hi-only, 256-wide)
    gemm_bf<256, 2, false><<<dim3(WCATN / 256, NN / 128), NTHR, SMEM_G4>>>(
        adjh, adjh, NN, T1th, T1tl, NN, Mb, nullptr, nullptr, WCATN, NN, 0, 0);

    // z / mu / logvar (+ z planes) + group evidence
    k_z     <<<(NN * (H2D / 8) + 255) / 256, 256>>>(Mb, eps_z, out_z, out_mu, out_lv, zh, zl);
    k_reduce<<<H2D, 256>>>(Mb);
    k_final <<<1, H2D>>>(eps_g, Wl, bl);
    k_bcast <<<(NN * H2D + 255) / 256, 256>>>(out_gmu, out_glv);

    // G5: uz planes = z @ Wl_top + crow   M=8192 N=128 K=128
    gemm_bf<128, 3, true><<<dim3(1, NN / 128), NTHR, SMEM_G1>>>(
        zh, zl, H2D, Wlth, Wltl, H2D, nullptr, uzh, uzl, H2D, H2D, 2, 0);
    // G6: recon = uz @ uz^T (fp32)        M=8192 N=8192 K=128 (256-wide tiles)
    gemm_bf<256, 2, true><<<dim3(NN / 256, NN / 128), NTHR, SMEM_G6>>>(
        uzh, uzl, H2D, uzh, uzl, H2D, out_recon, nullptr, nullptr, NN, H2D, 0, 0);
}

// round 17
// speedup vs baseline: 1.5428x; 1.1258x over previous
#include <cuda_runtime.h>
#include <cuda_bf16.h>
#include <cuda_fp16.h>
#include <cstdint>
#include <math.h>

// Problem sizes (fixed)
#define NN    8192
#define F_IN  512
#define H1D   256
#define H2D   128
#define WCATN 512   // 4*H2

typedef __nv_bfloat16 bf16;

// ---------------- scratch (device globals; no allocation allowed) -----------
// 16-bit planes stored TILED+SWIZZLED: logical [R][K] -> tiles (R/128)x(K/64),
// each tile 8192 elems = 16 KB contiguous, SW128-swizzled within.
// adj / T0t / T1t: SINGLE fp16 plane (eps_rel 2^-11; K=8192 paths).
// x / W* / h1 / z / uz: bf16 hi/lo double-split.
__device__ __half g_adjh[(size_t)NN * NN];
__device__ bf16 g_xh[NN * F_IN];
__device__ bf16 g_xl[NN * F_IN];
__device__ bf16 g_W1th[H1D * F_IN];
__device__ bf16 g_W1tl[H1D * F_IN];
__device__ bf16 g_Wcatth[WCATN * H1D];
__device__ bf16 g_Wcattl[WCATN * H1D];
__device__ bf16 g_Wlth[H2D * H2D];
__device__ bf16 g_Wltl[H2D * H2D];
__device__ __half g_T0th[H1D * NN];
__device__ bf16 g_h1h[NN * H1D];
__device__ bf16 g_h1l[NN * H1D];
__device__ __half g_T1th[WCATN * NN];
__device__ bf16 g_zh[NN * H2D];
__device__ bf16 g_zl[NN * H2D];
__device__ bf16 g_uzh[NN * H2D];
__device__ bf16 g_uzl[NN * H2D];
__device__ float g_Mb[NN * WCATN];
__device__ float g_prec[H2D];
__device__ float g_wmu[H2D];
__device__ float g_gmu[H2D];
__device__ float g_glv[H2D];
__device__ float g_crow[H2D];

// ---------------- common tile config ----------------------------------------
#define BKC        64
#define NTHR       256
#define SM_HDR     1024
#define PT_BYTES   16384                 // one stored 128x64 16-bit tile

#if defined(__CUDA_ARCH_FEAT_SM103_ALL) || defined(__CUDA_ARCH_FEAT_SM100_ALL)
#define HAVE_TCGEN05 1
#else
#define HAVE_TCGEN05 0
#endif

// header: [0] tmem ptr; full[s] @ 16+8s (s<6 -> 16..56); empty[s] @ 64+8s.
#define MB_FULL(base, s)  ((base) + 16 + 8 * (s))
#define MB_EMPTY(base, s) ((base) + 64 + 8 * (s))

// ---------------- tiled-plane addressing helpers -----------------------------
__host__ __device__ __forceinline__ size_t pt_base(int r, int k, int K) {
    return (((size_t)(r >> 7) * (size_t)(K >> 6)) + (size_t)(k >> 6)) << 13; // *8192
}
__device__ __forceinline__ uint32_t pt_sw(int rin, int kin) {
    uint32_t off = (uint32_t)(rin * 128 + kin * 2);
    return off ^ ((off >> 3) & 0x70);
}

__device__ __forceinline__ void split_bf(float v, bf16& h, bf16& l) {
    h = __float2bfloat16(v);
    l = __float2bfloat16(v - __bfloat162float(h));
}
__device__ __forceinline__ uint32_t pack2u(uint16_t a, uint16_t b) {
    return (uint32_t)a | ((uint32_t)b << 16);
}
__device__ __forceinline__ uint16_t bf_bits(bf16 v) { return *(uint16_t*)&v; }
__device__ __forceinline__ uint32_t elect_one_pred() {
    uint32_t pred;
    asm volatile(
        "{\n\t.reg .pred p;\n\telect.sync _|p, 0xFFFFFFFF;\n\tselp.b32 %0, 1, 0, p;\n\t}"
        : "=r"(pred));
    return pred;
}
__device__ __forceinline__ uint32_t smem_to_u32(const void* smem_ptr) {
    uint32_t addr;
    asm("{ .reg .u64 tmp; cvta.to.shared.u64 tmp, %1; cvt.u32.u64 %0, tmp; }"
        : "=r"(addr) : "l"(smem_ptr));
    return addr;
}

#if HAVE_TCGEN05

#define MBARRIER_INIT(mbar, count) \
    asm volatile("mbarrier.init.shared.b64 [%0], %1;" \
        :: "r"((uint32_t)(mbar)), "r"((uint32_t)(count)) : "memory")
#define MBARRIER_EXPECT_TX(mbar, tx) \
    asm volatile("mbarrier.arrive.expect_tx.shared.b64 _, [%0], %1;" \
        :: "r"((uint32_t)(mbar)), "r"((uint32_t)(tx)) : "memory")
#define BULK_G2S(dst_smem, src_gmem, bytes, mbar) \
    asm volatile("cp.async.bulk.shared::cta.global.mbarrier::complete_tx::bytes " \
        "[%0], [%1], %2, [%3];" \
        :: "r"((uint32_t)(dst_smem)), "l"(src_gmem), "r"((uint32_t)(bytes)), \
           "r"((uint32_t)(mbar)) : "memory")
#define MBARRIER_WAIT_PARITY(mbar_smem_addr, phase_parity) do { \
    uint32_t _mbar = (uint32_t)(mbar_smem_addr); \
    uint32_t _parity = (uint32_t)(phase_parity); \
    uint32_t _done; \
    asm volatile( \
        "{\n\t.reg .pred p;\n\t" \
        "mbarrier.try_wait.parity.acquire.cta.shared::cta.b64 p, [%1], %2;\n\t" \
        "selp.b32 %0, 1, 0, p;\n\t}" \
        : "=r"(_done) : "r"(_mbar), "r"(_parity) : "memory"); \
    if (!_done) { \
        asm volatile( \
            "{\n\t.reg .pred P1;\n\t" \
            "WAIT_LOOP_%=:\n\t" \
            "mbarrier.try_wait.parity.acquire.cta.shared::cta.b64 P1, [%0], %1, 0x989680;\n\t" \
            "@P1 bra.uni WAIT_DONE_%=;\n\t" \
            "bra.uni WAIT_LOOP_%=;\n\t" \
            "WAIT_DONE_%=:\n\t}" \
            :: "r"(_mbar), "r"(_parity) : "memory"); \
    } \
} while(0)

#define TCGEN05_ALLOC(smem_result_addr, nCols) \
    asm volatile("tcgen05.alloc.cta_group::1.sync.aligned.shared::cta.b32 [%0], %1;" \
        :: "r"((uint32_t)(smem_result_addr)), "r"((uint32_t)(nCols)) : "memory")
#define TCGEN05_DEALLOC(tmem_addr, nCols) \
    asm volatile("tcgen05.dealloc.cta_group::1.sync.aligned.b32 %0, %1;" \
        :: "r"(tmem_addr), "r"((uint32_t)(nCols)))
#define TCGEN05_RELINQUISH() \
    asm volatile("tcgen05.relinquish_alloc_permit.cta_group::1.sync.aligned;")
#define TCGEN05_COMMIT(mbar_smem_addr) \
    asm volatile("tcgen05.commit.cta_group::1.mbarrier::arrive::one.shared::cluster.b64 [%0];" \
        :: "r"((uint32_t)(mbar_smem_addr)) : "memory")
#define TCGEN05_WAIT_LD() \
    asm volatile("tcgen05.wait::ld.sync.aligned;" ::: "memory")
#define TCGEN05_FENCE_AFTER() \
    asm volatile("tcgen05.fence::after_thread_sync;" ::: "memory")

#define TCGEN05_LD_32X32B_X32(r, tmem_addr) \
    asm volatile( \
        "tcgen05.ld.sync.aligned.32x32b.x32.b32 " \
        "{%0, %1, %2, %3, %4, %5, %6, %7, " \
        " %8, %9, %10, %11, %12, %13, %14, %15, " \
        " %16, %17, %18, %19, %20, %21, %22, %23, " \
        " %24, %25, %26, %27, %28, %29, %30, %31}, [%32];" \
        : "=r"((r)[0]),  "=r"((r)[1]),  "=r"((r)[2]),  "=r"((r)[3]), \
          "=r"((r)[4]),  "=r"((r)[5]),  "=r"((r)[6]),  "=r"((r)[7]), \
          "=r"((r)[8]),  "=r"((r)[9]),  "=r"((r)[10]), "=r"((r)[11]), \
          "=r"((r)[12]), "=r"((r)[13]), "=r"((r)[14]), "=r"((r)[15]), \
          "=r"((r)[16]), "=r"((r)[17]), "=r"((r)[18]), "=r"((r)[19]), \
          "=r"((r)[20]), "=r"((r)[21]), "=r"((r)[22]), "=r"((r)[23]), \
          "=r"((r)[24]), "=r"((r)[25]), "=r"((r)[26]), "=r"((r)[27]), \
          "=r"((r)[28]), "=r"((r)[29]), "=r"((r)[30]), "=r"((r)[31]) \
        : "r"(tmem_addr))

static constexpr uint64_t SMEM_DESC_BASE_SW128 =
    (uint64_t(2)  << 61) | (uint64_t(1) << 46) | (uint64_t(64) << 32) | (uint64_t(1) << 16);
#define MAKE_SMEM_DESC(base_addr) \
    (SMEM_DESC_BASE_SW128 | ((uint64_t)((base_addr) >> 4) & 0x3FFF))

__device__ __forceinline__ void mma_f16k(uint32_t d, uint64_t ad, uint64_t bd,
                                         uint32_t idesc, uint32_t en) {
    asm volatile(
        "{\n\t.reg .pred p;\n\tsetp.ne.u32 p, %4, 0;\n\t"
        "tcgen05.mma.cta_group::1.kind::f16 [%0], %1, %2, %3, {%5,%5,%5,%5}, p;\n\t}"
        :: "r"(d), "l"(ad), "l"(bd), "r"(idesc), "r"(en), "r"(0u) : "memory");
}
#endif  // HAVE_TCGEN05

// ---------------- GEMM: C = A[M,K] @ Bt[N,K]^T via tiled 16-bit planes ------
// TN: tile N; NS: ring depth; HAL/HBL: lo planes present; F16IN: A/B are fp16
// (else bf16); F16OUT: Ch plane written as fp16 (hi-only).
// Pipeline: full-NS prologue, refill after own-commit wait (lap-free).
// epi: 0 none, 1 relu, 2 add g_crow; transC: output transposed.
template<int TN, int NS, bool HAL, bool HBL, bool F16IN, bool F16OUT>
__global__ void __launch_bounds__(NTHR, 1)
gemm_bf(const uint16_t* __restrict__ Ah, const uint16_t* __restrict__ Al, int lda,
        const uint16_t* __restrict__ Bh, const uint16_t* __restrict__ Bl, int ldb,
        float* __restrict__ C, uint16_t* __restrict__ Ch, uint16_t* __restrict__ Cl,
        int ldc, int K, int epi, int transC)
{
    extern __shared__ char smem[];
    const int tid = threadIdx.x;
    const int col0 = blockIdx.x * TN;
    const int row0 = blockIdx.y * 128;

    constexpr int NBT = TN / 128;
    constexpr int ATL = HAL ? 2 : 1;
    constexpr int BTL = (HBL ? 2 : 1) * NBT;
    constexpr int STAGE_BYTES = (ATL + BTL) * PT_BYTES;

#if HAVE_TCGEN05
    const uint32_t smem_base = smem_to_u32(smem);
    const int wid = tid >> 5;
    const int lid = tid & 31;

    // kind::f16 idesc: dtype F32@4, atype@7 (F16=0, BF16=1), btype@10
    constexpr uint32_t DT = F16IN ? 0u : 1u;
    constexpr uint32_t IDESC =
        (1u << 4) | (DT << 7) | (DT << 10) | ((TN / 8) << 17) | ((128 / 16) << 24);

    if (wid == 0) TCGEN05_ALLOC(smem_base + 0, TN);
    if (tid == 0) {
#pragma unroll
        for (int s = 0; s < NS; ++s) {
            MBARRIER_INIT(MB_FULL(smem_base, s), 1);
            MBARRIER_INIT(MB_EMPTY(smem_base, s), 1);
        }
    }
    __syncthreads();
    uint32_t tmem;
    asm volatile("ld.shared.b32 %0, [%1];" : "=r"(tmem) : "r"(smem_base));

    const int nch = K / BKC;

    if (wid == 0 && elect_one_pred()) {
        auto load_chunk = [&](int n, int s) {
            uint32_t dst = smem_base + SM_HDR + s * STAGE_BYTES;
            uint32_t fb = MB_FULL(smem_base, s);
            MBARRIER_EXPECT_TX(fb, STAGE_BYTES);
            BULK_G2S(dst, Ah + pt_base(row0, n * BKC, lda), PT_BYTES, fb);
            if (HAL)
                BULK_G2S(dst + PT_BYTES, Al + pt_base(row0, n * BKC, lda), PT_BYTES, fb);
#pragma unroll
            for (int t = 0; t < NBT; ++t) {
                BULK_G2S(dst + (ATL + t) * PT_BYTES,
                         Bh + pt_base(col0 + t * 128, n * BKC, ldb), PT_BYTES, fb);
                if (HBL)
                    BULK_G2S(dst + (ATL + NBT + t) * PT_BYTES,
                             Bl + pt_base(col0 + t * 128, n * BKC, ldb), PT_BYTES, fb);
            }
        };

        const int P = (nch < NS) ? nch : NS;
        for (int p = 0; p < P; ++p) load_chunk(p, p);

        for (int c = 0; c < nch; ++c) {
            const int ci = c / NS;
            const int s  = c - ci * NS;
            MBARRIER_WAIT_PARITY(MB_FULL(smem_base, s), ci & 1);
            uint32_t stg = smem_base + SM_HDR + s * STAGE_BYTES;
            uint64_t ah = MAKE_SMEM_DESC(stg);
            uint64_t al = ah + (PT_BYTES >> 4);
            uint64_t bh = ah + ATL * (PT_BYTES >> 4);
            uint64_t bl = bh + NBT * (PT_BYTES >> 4);
            uint32_t en = (c > 0) ? 1u : 0u;
#pragma unroll
            for (int st = 0; st < 4; ++st) {     // 4 k-steps of 16 elems
                mma_f16k(tmem, ah + 2 * st, bh + 2 * st, IDESC, en); en = 1u;
                if (HBL) mma_f16k(tmem, ah + 2 * st, bl + 2 * st, IDESC, 1u);
                if (HAL) mma_f16k(tmem, al + 2 * st, bh + 2 * st, IDESC, 1u);
            }
            TCGEN05_COMMIT(MB_EMPTY(smem_base, s));
            const int n = c + NS;
            if (n < nch) {
                MBARRIER_WAIT_PARITY(MB_EMPTY(smem_base, s), ci & 1);
                load_chunk(n, s);
            }
        }
        const int cl = nch - 1;
        MBARRIER_WAIT_PARITY(MB_EMPTY(smem_base, cl % NS), (cl / NS) & 1);
    }
    __syncthreads();
    TCGEN05_FENCE_AFTER();

    // epilogue: 8 warps; warps 0-3 = first half of col groups, 4-7 = second half
    {
        constexpr int NGRP = TN / 32;
        constexpr int HALF = NGRP / 2;
        const int wg = wid >> 2;
        const int row = row0 + (wid & 3) * 32 + lid;
#pragma unroll
        for (int gg = 0; gg < HALF; ++gg) {
            const int g = wg * HALF + gg;
            uint32_t r[32];
            TCGEN05_LD_32X32B_X32(r, tmem + g * 32);
            TCGEN05_WAIT_LD();
            if (C) {
#pragma unroll
                for (int j = 0; j < 32; j += 4) {
                    const int col = col0 + g * 32 + j;
                    float v0 = __uint_as_float(r[j + 0]);
                    float v1 = __uint_as_float(r[j + 1]);
                    float v2 = __uint_as_float(r[j + 2]);
                    float v3 = __uint_as_float(r[j + 3]);
                    if (epi == 1) {
                        v0 = fmaxf(v0, 0.0f); v1 = fmaxf(v1, 0.0f);
                        v2 = fmaxf(v2, 0.0f); v3 = fmaxf(v3, 0.0f);
                    } else if (epi == 2) {
                        v0 += g_crow[col + 0]; v1 += g_crow[col + 1];
                        v2 += g_crow[col + 2]; v3 += g_crow[col + 3];
                    }
                    if (!transC) {
                        *(float4*)(C + (size_t)row * ldc + col) = make_float4(v0, v1, v2, v3);
                    } else {
                        C[(size_t)(col + 0) * ldc + row] = v0;
                        C[(size_t)(col + 1) * ldc + row] = v1;
                        C[(size_t)(col + 2) * ldc + row] = v2;
                        C[(size_t)(col + 3) * ldc + row] = v3;
                    }
                }
            }
            if (Ch) {
#pragma unroll
                for (int j = 0; j < 32; j += 8) {
                    const int colb = col0 + g * 32 + j;
                    float v[8];
#pragma unroll
                    for (int q = 0; q < 8; ++q) {
                        float t = __uint_as_float(r[j + q]);
                        if (epi == 1) t = fmaxf(t, 0.0f);
                        else if (epi == 2) t += g_crow[colb + q];
                        v[q] = t;
                    }
                    uint16_t h[8], l[8];
                    if (Cl) {
#pragma unroll
                        for (int q = 0; q < 8; ++q) {
                            bf16 hh, ll; split_bf(v[q], hh, ll);
                            h[q] = bf_bits(hh); l[q] = bf_bits(ll);
                        }
                    } else if (F16OUT) {
#pragma unroll
                        for (int q = 0; q < 8; ++q) {
                            __half hv = __float2half(v[q]);
                            h[q] = *(uint16_t*)&hv;
                        }
                    } else {
#pragma unroll
                        for (int q = 0; q < 8; ++q) {
                            bf16 hv = __float2bfloat16(v[q]);
                            h[q] = bf_bits(hv);
                        }
                    }
                    if (!transC) {
                        size_t tb = pt_base(row, colb, ldc);
                        uint32_t sw = pt_sw(row & 127, colb & 63);
                        *(uint4*)((char*)(Ch + tb) + sw) =
                            make_uint4(pack2u(h[0], h[1]), pack2u(h[2], h[3]),
                                       pack2u(h[4], h[5]), pack2u(h[6], h[7]));
                        if (Cl)
                            *(uint4*)((char*)(Cl + tb) + sw) =
                                make_uint4(pack2u(l[0], l[1]), pack2u(l[2], l[3]),
                                           pack2u(l[4], l[5]), pack2u(l[6], l[7]));
                    } else {
#pragma unroll
                        for (int q = 0; q < 8; ++q) {
                            const int col = colb + q;
                            size_t tb = pt_base(col, row, ldc);
                            uint32_t sw = pt_sw(col & 127, row & 63);
                            *(uint16_t*)((char*)(Ch + tb) + sw) = h[q];
                            if (Cl) *(uint16_t*)((char*)(Cl + tb) + sw) = l[q];
                        }
                    }
                }
            }
        }
    }
    __syncthreads();
    if (tid == 0) {
#pragma unroll
        for (int s = 0; s < NS; ++s) {
            asm volatile("mbarrier.inval.shared.b64 [%0];" :: "r"(MB_FULL(smem_base, s)) : "memory");
            asm volatile("mbarrier.inval.shared.b64 [%0];" :: "r"(MB_EMPTY(smem_base, s)) : "memory");
        }
    }
    __syncthreads();
    if (wid == 0) {
        TCGEN05_RELINQUISH();
        TCGEN05_DEALLOC(tmem, TN);
    }

#else
    // ------------- fallback (compile-only on non-103a passes) ---------------
    float* As = (float*)smem;                 // [16][128]
    float* Bs = As + 16 * 128;
    const int tx = tid & 15;
    const int ty = tid >> 4;

    auto dec = [](uint16_t bits) {
        if (F16IN) { __half h = *(__half*)&bits; return __half2float(h); }
        bf16 b = *(bf16*)&bits; return __bfloat162float(b);
    };
    auto rdp = [&](const uint16_t* P, int r, int k, int Kl) {
        size_t tb = pt_base(r, k, Kl);
        uint32_t sw = pt_sw(r & 127, k & 63);
        return dec(*(const uint16_t*)((const char*)(P + tb) + sw));
    };
    for (int cb = 0; cb < TN / 128; ++cb) {
        const int cbase = col0 + cb * 128;
        float acc[8][8];
#pragma unroll
        for (int i = 0; i < 8; i++)
#pragma unroll
            for (int j = 0; j < 8; j++) acc[i][j] = 0.0f;
        for (int k0 = 0; k0 < K; k0 += 16) {
            __syncthreads();
            for (int f = tid; f < 16 * 128; f += NTHR) {
                int kk = f >> 7, m = f & 127;
                float av = rdp(Ah, row0 + m, k0 + kk, lda);
                if (HAL) av += rdp(Al, row0 + m, k0 + kk, lda);
                As[kk * 128 + m] = av;
                float bv = rdp(Bh, cbase + m, k0 + kk, ldb);
                if (HBL) bv += rdp(Bl, cbase + m, k0 + kk, ldb);
                Bs[kk * 128 + m] = bv;
            }
            __syncthreads();
#pragma unroll
            for (int kk = 0; kk < 16; kk++) {
                float a[8], b[8];
#pragma unroll
                for (int i = 0; i < 8; i++) a[i] = As[kk * 128 + ty * 8 + i];
#pragma unroll
                for (int j = 0; j < 8; j++) b[j] = Bs[kk * 128 + tx * 8 + j];
#pragma unroll
                for (int i = 0; i < 8; i++)
#pragma unroll
                    for (int j = 0; j < 8; j++) acc[i][j] = fmaf(a[i], b[j], acc[i][j]);
            }
        }
#pragma unroll
        for (int i = 0; i < 8; i++) {
            const int row = row0 + ty * 8 + i;
#pragma unroll
            for (int j = 0; j < 8; j++) {
                const int col = cbase + tx * 8 + j;
                float v = acc[i][j];
                if (epi == 1) v = fmaxf(v, 0.0f);
                else if (epi == 2) v += g_crow[col];
                if (C) {
                    size_t idx = transC ? ((size_t)col * ldc + row) : ((size_t)row * ldc + col);
                    C[idx] = v;
                }
                if (Ch) {
                    uint16_t hb, lb;
                    if (Cl) {
                        bf16 hh, ll; split_bf(v, hh, ll);
                        hb = bf_bits(hh); lb = bf_bits(ll);
                    } else if (F16OUT) {
                        __half hv = __float2half(v); hb = *(uint16_t*)&hv; lb = 0;
                    } else {
                        bf16 hv = __float2bfloat16(v); hb = bf_bits(hv); lb = 0;
                    }
                    int pr = transC ? col : row;
                    int pk = transC ? row : col;
                    size_t tb = pt_base(pr, pk, ldc);
                    uint32_t sw = pt_sw(pr & 127, pk & 63);
                    *(uint16_t*)((char*)(Ch + tb) + sw) = hb;
                    if (Cl) *(uint16_t*)((char*)(Cl + tb) + sw) = lb;
                }
            }
        }
        __syncthreads();
    }
#endif
}

// ---------------- split kernels (write tiled plane layout) -------------------
// fp16 single-plane split (adj)
__global__ void k_split_f16(const float* __restrict__ src, __half* __restrict__ dh,
                            int R, int K) {
    size_t idx = (size_t)blockIdx.x * blockDim.x + threadIdx.x;
    size_t n8 = (size_t)K >> 3;
    if (idx >= (size_t)R * n8) return;
    int r = (int)(idx / n8);
    int k = (int)(idx % n8) * 8;
    float4 a = *(const float4*)(src + (size_t)r * K + k);
    float4 b = *(const float4*)(src + (size_t)r * K + k + 4);
    __half h[8];
    h[0] = __float2half(a.x); h[1] = __float2half(a.y);
    h[2] = __float2half(a.z); h[3] = __float2half(a.w);
    h[4] = __float2half(b.x); h[5] = __float2half(b.y);
    h[6] = __float2half(b.z); h[7] = __float2half(b.w);
    size_t tb = pt_base(r, k, K);
    uint32_t sw = pt_sw(r & 127, k & 63);
    uint16_t* u = (uint16_t*)h;
    *(uint4*)((char*)(dh + tb) + sw) = make_uint4(pack2u(u[0], u[1]), pack2u(u[2], u[3]),
                                                  pack2u(u[4], u[5]), pack2u(u[6], u[7]));
}

__global__ void k_split_tiled(const float* __restrict__ src, bf16* __restrict__ dh,
                              bf16* __restrict__ dl, int R, int K) {
    size_t idx = (size_t)blockIdx.x * blockDim.x + threadIdx.x;
    size_t n8 = (size_t)K >> 3;
    if (idx >= (size_t)R * n8) return;
    int r = (int)(idx / n8);
    int k = (int)(idx % n8) * 8;
    float4 a = *(const float4*)(src + (size_t)r * K + k);
    float4 b = *(const float4*)(src + (size_t)r * K + k + 4);
    bf16 h[8], l[8];
    split_bf(a.x, h[0], l[0]); split_bf(a.y, h[1], l[1]);
    split_bf(a.z, h[2], l[2]); split_bf(a.w, h[3], l[3]);
    split_bf(b.x, h[4], l[4]); split_bf(b.y, h[5], l[5]);
    split_bf(b.z, h[6], l[6]); split_bf(b.w, h[7], l[7]);
    size_t tb = pt_base(r, k, K);
    uint32_t sw = pt_sw(r & 127, k & 63);
    *(uint4*)((char*)(dh + tb) + sw) = make_uint4(pack2u(bf_bits(h[0]), bf_bits(h[1])),
                                                  pack2u(bf_bits(h[2]), bf_bits(h[3])),
                                                  pack2u(bf_bits(h[4]), bf_bits(h[5])),
                                                  pack2u(bf_bits(h[6]), bf_bits(h[7])));
    *(uint4*)((char*)(dl + tb) + sw) = make_uint4(pack2u(bf_bits(l[0]), bf_bits(l[1])),
                                                  pack2u(bf_bits(l[2]), bf_bits(l[3])),
                                                  pack2u(bf_bits(l[4]), bf_bits(l[5])),
                                                  pack2u(bf_bits(l[6]), bf_bits(l[7])));
}

__global__ void k_split_T(const float* __restrict__ src, bf16* __restrict__ dh,
                          bf16* __restrict__ dl, int R, int K) {
    int idx = blockIdx.x * blockDim.x + threadIdx.x;
    int n8 = K >> 3;
    if (idx >= R * n8) return;
    int r = idx / n8;
    int k = (idx % n8) * 8;
    bf16 h[8], l[8];
#pragma unroll
    for (int q = 0; q < 8; ++q) split_bf(src[(size_t)(k + q) * R + r], h[q], l[q]);
    size_t tb = pt_base(r, k, K);
    uint32_t sw = pt_sw(r & 127, k & 63);
    *(uint4*)((char*)(dh + tb) + sw) = make_uint4(pack2u(bf_bits(h[0]), bf_bits(h[1])),
                                                  pack2u(bf_bits(h[2]), bf_bits(h[3])),
                                                  pack2u(bf_bits(h[4]), bf_bits(h[5])),
                                                  pack2u(bf_bits(h[6]), bf_bits(h[7])));
    *(uint4*)((char*)(dl + tb) + sw) = make_uint4(pack2u(bf_bits(l[0]), bf_bits(l[1])),
                                                  pack2u(bf_bits(l[2]), bf_bits(l[3])),
                                                  pack2u(bf_bits(l[4]), bf_bits(l[5])),
                                                  pack2u(bf_bits(l[6]), bf_bits(l[7])));
}

__global__ void k_split_wcatt(const float* __restrict__ W2, const float* __restrict__ W3,
                              const float* __restrict__ W4, const float* __restrict__ W5,
                              bf16* __restrict__ dh, bf16* __restrict__ dl) {
    int idx = blockIdx.x * blockDim.x + threadIdx.x;
    int n8 = H1D >> 3;
    if (idx >= WCATN * n8) return;
    int n = idx / n8;
    int k = (idx % n8) * 8;
    int sel = n >> 7, nn = n & (H2D - 1);
    const float* W = (sel == 0) ? W2 : (sel == 1) ? W3 : (sel == 2) ? W4 : W5;
    bf16 h[8], l[8];
#pragma unroll
    for (int q = 0; q < 8; ++q) split_bf(W[(size_t)(k + q) * H2D + nn], h[q], l[q]);
    size_t tb = pt_base(n, k, H1D);
    uint32_t sw = pt_sw(n & 127, k & 63);
    *(uint4*)((char*)(dh + tb) + sw) = make_uint4(pack2u(bf_bits(h[0]), bf_bits(h[1])),
                                                  pack2u(bf_bits(h[2]), bf_bits(h[3])),
                                                  pack2u(bf_bits(h[4]), bf_bits(h[5])),
                                                  pack2u(bf_bits(h[6]), bf_bits(h[7])));
    *(uint4*)((char*)(dl + tb) + sw) = make_uint4(pack2u(bf_bits(l[0]), bf_bits(l[1])),
                                                  pack2u(bf_bits(l[2]), bf_bits(l[3])),
                                                  pack2u(bf_bits(l[4]), bf_bits(l[5])),
                                                  pack2u(bf_bits(l[6]), bf_bits(l[7])));
}

__global__ void k_z(const float* __restrict__ Mb, const float* __restrict__ eps_z,
                    float* __restrict__ out_z, float* __restrict__ out_mu,
                    float* __restrict__ out_lv, bf16* __restrict__ zh,
                    bf16* __restrict__ zl) {
    int idx = blockIdx.x * blockDim.x + threadIdx.x;
    if (idx >= NN * (H2D / 8)) return;
    int i = idx / (H2D / 8);
    int j = (idx % (H2D / 8)) * 8;
    float4 mu0 = *(const float4*)(Mb + (size_t)i * WCATN + j);
    float4 mu1 = *(const float4*)(Mb + (size_t)i * WCATN + j + 4);
    float4 lv0 = *(const float4*)(Mb + (size_t)i * WCATN + H2D + j);
    float4 lv1 = *(const float4*)(Mb + (size_t)i * WCATN + H2D + j + 4);
    float4 e0 = *(const float4*)(eps_z + (size_t)i * H2D + j);
    float4 e1 = *(const float4*)(eps_z + (size_t)i * H2D + j + 4);
    *(float4*)(out_mu + (size_t)i * H2D + j) = mu0;
    *(float4*)(out_mu + (size_t)i * H2D + j + 4) = mu1;
    *(float4*)(out_lv + (size_t)i * H2D + j) = lv0;
    *(float4*)(out_lv + (size_t)i * H2D + j + 4) = lv1;
    float z[8];
    z[0] = e0.x * expf(lv0.x) + mu0.x; z[1] = e0.y * expf(lv0.y) + mu0.y;
    z[2] = e0.z * expf(lv0.z) + mu0.z; z[3] = e0.w * expf(lv0.w) + mu0.w;
    z[4] = e1.x * expf(lv1.x) + mu1.x; z[5] = e1.y * expf(lv1.y) + mu1.y;
    z[6] = e1.z * expf(lv1.z) + mu1.z; z[7] = e1.w * expf(lv1.w) + mu1.w;
    *(float4*)(out_z + (size_t)i * H2D + j) = make_float4(z[0], z[1], z[2], z[3]);
    *(float4*)(out_z + (size_t)i * H2D + j + 4) = make_float4(z[4], z[5], z[6], z[7]);
    bf16 h[8], l[8];
#pragma unroll
    for (int q = 0; q < 8; ++q) split_bf(z[q], h[q], l[q]);
    size_t tb = pt_base(i, j, H2D);
    uint32_t sw = pt_sw(i & 127, j & 63);
    *(uint4*)((char*)(zh + tb) + sw) = make_uint4(pack2u(bf_bits(h[0]), bf_bits(h[1])),
                                                  pack2u(bf_bits(h[2]), bf_bits(h[3])),
                                                  pack2u(bf_bits(h[4]), bf_bits(h[5])),
                                                  pack2u(bf_bits(h[6]), bf_bits(h[7])));
    *(uint4*)((char*)(zl + tb) + sw) = make_uint4(pack2u(bf_bits(l[0]), bf_bits(l[1])),
                                                  pack2u(bf_bits(l[2]), bf_bits(l[3])),
                                                  pack2u(bf_bits(l[4]), bf_bits(l[5])),
                                                  pack2u(bf_bits(l[6]), bf_bits(l[7])));
}

__global__ void k_reduce(const float* __restrict__ Mb) {
    __shared__ float s1[256];
    __shared__ float s2[256];
    int j = blockIdx.x, t = threadIdx.x;
    float a = 0.0f, b = 0.0f;
    for (int i = t; i < NN; i += 256) {
        float cm = Mb[(size_t)i * WCATN + 2 * H2D + j];
        float cl = Mb[(size_t)i * WCATN + 3 * H2D + j];
        float var = expf(cl);
        if (var == 0.0f) var = 1e-6f;
        float inv = 1.0f / var;
        a += inv;
        b += cm * inv;
    }
    s1[t] = a; s2[t] = b;
    __syncthreads();
    for (int s = 128; s > 0; s >>= 1) {
        if (t < s) { s1[t] += s1[t + s]; s2[t] += s2[t + s]; }
        __syncthreads();
    }
    if (t == 0) { g_prec[j] = s1[0]; g_wmu[j] = s2[0]; }
}

__global__ void k_final(const float* __restrict__ eps_g, const float* __restrict__ Wl,
                        const float* __restrict__ bl) {
    __shared__ float cl_sh[H2D];
    int j = threadIdx.x;
    float gvar = 1.0f / g_prec[j];
    float gmu = gvar * g_wmu[j];
    float gv = (gvar == 0.0f) ? 1e-6f : gvar;
    float glv = logf(gv);
    float cl = gmu + expf(0.5f * glv) * eps_g[j];
    g_gmu[j] = gmu;
    g_glv[j] = glv;
    cl_sh[j] = cl;
    __syncthreads();
    float s = bl[j];
#pragma unroll 8
    for (int k = 0; k < H2D; k++)
        s = fmaf(cl_sh[k], Wl[(H2D + k) * H2D + j], s);
    g_crow[j] = s;
}

__global__ void k_bcast(float* __restrict__ out_gmu, float* __restrict__ out_glv) {
    int idx = blockIdx.x * blockDim.x + threadIdx.x;
    if (idx >= NN * H2D) return;
    int j = idx & (H2D - 1);
    out_gmu[idx] = g_gmu[j];
    out_glv[idx] = g_glv[j];
}

// ---------------- launch ----------------------------------------------------
extern "C" void kernel_launch(void* const* d_in, const int* in_sizes, int n_in,
                              void* d_out, int out_size)
{
    const float* x     = (const float*)d_in[0];
    const float* adj   = (const float*)d_in[1];
    const float* W1    = (const float*)d_in[2];
    const float* W2    = (const float*)d_in[3];
    const float* W3    = (const float*)d_in[4];
    const float* W4    = (const float*)d_in[5];
    const float* W5    = (const float*)d_in[6];
    const float* Wl    = (const float*)d_in[7];
    const float* bl    = (const float*)d_in[8];
    const float* eps_z = (const float*)d_in[9];
    const float* eps_g = (const float*)d_in[10];

    float* out = (float*)d_out;
    float* out_recon = out;
    float* out_z     = out + (size_t)NN * NN;
    float* out_mu    = out_z  + (size_t)NN * H2D;
    float* out_lv    = out_mu + (size_t)NN * H2D;
    float* out_gmu   = out_lv + (size_t)NN * H2D;
    float* out_glv   = out_gmu + (size_t)NN * H2D;

    __half *adjh, *T0th, *T1th;
    bf16 *xh, *xl, *W1th, *W1tl, *Wcatth, *Wcattl, *Wlth, *Wltl;
    bf16 *h1h, *h1l, *zh, *zl, *uzh, *uzl;
    float *Mb;
    cudaGetSymbolAddress((void**)&adjh,   g_adjh);
    cudaGetSymbolAddress((void**)&xh,     g_xh);
    cudaGetSymbolAddress((void**)&xl,     g_xl);
    cudaGetSymbolAddress((void**)&W1th,   g_W1th);
    cudaGetSymbolAddress((void**)&W1tl,   g_W1tl);
    cudaGetSymbolAddress((void**)&Wcatth, g_Wcatth);
    cudaGetSymbolAddress((void**)&Wcattl, g_Wcattl);
    cudaGetSymbolAddress((void**)&Wlth,   g_Wlth);
    cudaGetSymbolAddress((void**)&Wltl,   g_Wltl);
    cudaGetSymbolAddress((void**)&T0th,   g_T0th);
    cudaGetSymbolAddress((void**)&h1h,    g_h1h);
    cudaGetSymbolAddress((void**)&h1l,    g_h1l);
    cudaGetSymbolAddress((void**)&T1th,   g_T1th);
    cudaGetSymbolAddress((void**)&zh,     g_zh);
    cudaGetSymbolAddress((void**)&zl,     g_zl);
    cudaGetSymbolAddress((void**)&uzh,    g_uzh);
    cudaGetSymbolAddress((void**)&uzl,    g_uzl);
    cudaGetSymbolAddress((void**)&Mb,     g_Mb);

    // instantiations:
    // G1/G3: <128,3,true,true,false,true>   stage 64K x3
    // G2:    <128,6,false,false,true,false> stage 32K x6
    // G4:    <256,4,false,false,true,false> stage 48K x4
    // G5:    <128,3,true,true,false,false>  stage 64K x3
    // G6:    <256,2,true,true,false,false>  stage 96K x2
    const int SMEM_A = SM_HDR + 3 * 4 * PT_BYTES;
    const int SMEM_B = SM_HDR + 6 * 2 * PT_BYTES;
    const int SMEM_C = SM_HDR + 4 * 3 * PT_BYTES;
    const int SMEM_D = SM_HDR + 2 * 6 * PT_BYTES;
    cudaFuncSetAttribute(gemm_bf<128, 3, true,  true,  false, true >, cudaFuncAttributeMaxDynamicSharedMemorySize, SMEM_A);
    cudaFuncSetAttribute(gemm_bf<128, 6, false, false, true,  false>, cudaFuncAttributeMaxDynamicSharedMemorySize, SMEM_B);
    cudaFuncSetAttribute(gemm_bf<256, 4, false, false, true,  false>, cudaFuncAttributeMaxDynamicSharedMemorySize, SMEM_C);
    cudaFuncSetAttribute(gemm_bf<128, 3, true,  true,  false, false>, cudaFuncAttributeMaxDynamicSharedMemorySize, SMEM_A);
    cudaFuncSetAttribute(gemm_bf<256, 2, true,  true,  false, false>, cudaFuncAttributeMaxDynamicSharedMemorySize, SMEM_D);

    // input splits; adj = fp16 single plane
    {
        size_t na = (size_t)NN * (NN / 8);
        k_split_f16<<<(unsigned)((na + 255) / 256), 256>>>(adj, adjh, NN, NN);
        size_t nx = (size_t)NN * (F_IN / 8);
        k_split_tiled<<<(unsigned)((nx + 255) / 256), 256>>>(x, xh, xl, NN, F_IN);
        k_split_T<<<(H1D * F_IN / 8 + 255) / 256, 256>>>(W1, W1th, W1tl, H1D, F_IN);
        k_split_wcatt<<<(WCATN * H1D / 8 + 255) / 256, 256>>>(W2, W3, W4, W5, Wcatth, Wcattl);
        k_split_T<<<(H2D * H2D / 8 + 255) / 256, 256>>>(Wl, Wlth, Wltl, H2D, H2D);
    }

    // G1: T0t (fp16 hi) = (x @ W1)^T   M=8192 N=256 K=512
    gemm_bf<128, 3, true, true, false, true><<<dim3(H1D / 128, NN / 128), NTHR, SMEM_A>>>(
        (const uint16_t*)xh, (const uint16_t*)xl, F_IN,
        (const uint16_t*)W1th, (const uint16_t*)W1tl, F_IN,
        nullptr, (uint16_t*)T0th, nullptr, NN, F_IN, 0, 1);
    // G2: h1 planes = relu(adj @ T0)  M=8192 N=256 K=8192 (fp16 x fp16, NS=6)
    gemm_bf<128, 6, false, false, true, false><<<dim3(H1D / 128, NN / 128), NTHR, SMEM_B>>>(
        (const uint16_t*)adjh, nullptr, NN,
        (const uint16_t*)T0th, nullptr, NN,
        nullptr, (uint16_t*)h1h, (uint16_t*)h1l, H1D, NN, 1, 0);
    // G3: T1t (fp16 hi) = (h1 @ Wcat)^T  M=8192 N=512 K=256
    gemm_bf<128, 3, true, true, false, true><<<dim3(WCATN / 128, NN / 128), NTHR, SMEM_A>>>(
        (const uint16_t*)h1h, (const uint16_t*)h1l, H1D,
        (const uint16_t*)Wcatth, (const uint16_t*)Wcattl, H1D,
        nullptr, (uint16_t*)T1th, nullptr, NN, H1D, 0, 1);
    // G4: Mb = adj @ T1 (fp32)   M=8192 N=512 K=8192 (fp16 x fp16, 256-wide, NS=4)
    gemm_bf<256, 4, false, false, true, false><<<dim3(WCATN / 256, NN / 128), NTHR, SMEM_C>>>(
        (const uint16_t*)adjh, nullptr, NN,
        (const uint16_t*)T1th, nullptr, NN,
        Mb, nullptr, nullptr, WCATN, NN, 0, 0);

    // z / mu / logvar (+ z planes) + group evidence
    k_z     <<<(NN * (H2D / 8) + 255) / 256, 256>>>(Mb, eps_z, out_z, out_mu, out_lv, zh, zl);
    k_reduce<<<H2D, 256>>>(Mb);
    k_final <<<1, H2D>>>(eps_g, Wl, bl);
    k_bcast <<<(NN * H2D + 255) / 256, 256>>>(out_gmu, out_glv);

    // G5: uz planes = z @ Wl_top + crow   M=8192 N=128 K=128 (bf16 double)
    gemm_bf<128, 3, true, true, false, false><<<dim3(1, NN / 128), NTHR, SMEM_A>>>(
        (const uint16_t*)zh, (const uint16_t*)zl, H2D,
        (const uint16_t*)Wlth, (const uint16_t*)Wltl, H2D,
        nullptr, (uint16_t*)uzh, (uint16_t*)uzl, H2D, H2D, 2, 0);
    // G6: recon = uz @ uz^T (fp32)        M=8192 N=8192 K=128 (bf16 double, 256-wide)
    gemm_bf<256, 2, true, true, false, false><<<dim3(NN / 256, NN / 128), NTHR, SMEM_D>>>(
        (const uint16_t*)uzh, (const uint16_t*)uzl, H2D,
        (const uint16_t*)uzh, (const uint16_t*)uzl, H2D,
        out_recon, nullptr, nullptr, NN, H2D, 0, 0);
}